// round 12
// baseline (speedup 1.0000x reference)
#include <cuda_runtime.h>
#include <cuda_fp16.h>
#include <cstdint>

#define BB 2
#define LL 2048
#define HID 1024
#define NH 16
#define FDIM 16
#define HDIM 64
#define MTOT (BB*LL)   // 4096
#define BK 16

// Scratch (static __device__ — no allocation allowed)
__device__ float g_q[MTOT * NH * FDIM];   // 4 MB
__device__ float g_k[MTOT * NH * FDIM];   // 4 MB
__device__ float g_v[MTOT * HID];         // 16 MB
__device__ float g_o[MTOT * HID];         // 16 MB

// ---------------------------------------------------------------------------
// mma helpers (tf32 layouts validated R6/R7; f16 m16n8k16 layout per PTX ISA)
// ---------------------------------------------------------------------------
__device__ __forceinline__ void mma_tf32(float& d0, float& d1, float& d2, float& d3,
                                         uint32_t a0, uint32_t a1, uint32_t a2, uint32_t a3,
                                         uint32_t b0, uint32_t b1) {
    asm volatile("mma.sync.aligned.m16n8k8.row.col.f32.tf32.tf32.f32 "
                 "{%0,%1,%2,%3}, {%4,%5,%6,%7}, {%8,%9}, {%0,%1,%2,%3};"
                 : "+f"(d0), "+f"(d1), "+f"(d2), "+f"(d3)
                 : "r"(a0), "r"(a1), "r"(a2), "r"(a3), "r"(b0), "r"(b1));
}

__device__ __forceinline__ void mma_f16(float& d0, float& d1, float& d2, float& d3,
                                        uint32_t a0, uint32_t a1, uint32_t a2, uint32_t a3,
                                        uint32_t b0, uint32_t b1) {
    asm volatile("mma.sync.aligned.m16n8k16.row.col.f32.f16.f16.f32 "
                 "{%0,%1,%2,%3}, {%4,%5,%6,%7}, {%8,%9}, {%0,%1,%2,%3};"
                 : "+f"(d0), "+f"(d1), "+f"(d2), "+f"(d3)
                 : "r"(a0), "r"(a1), "r"(a2), "r"(a3), "r"(b0), "r"(b1));
}

__device__ __forceinline__ uint32_t f2tf(float f) {
    uint32_t u;
    asm("cvt.rna.tf32.f32 %0, %1;" : "=r"(u) : "f"(f));
    return u;
}

__device__ __forceinline__ uint32_t pack_h2(float lo, float hi) {
    __half2 h = __floats2half2_rn(lo, hi);   // .x = lo
    return *(uint32_t*)&h;
}

__device__ __forceinline__ uint32_t sptr(const void* p) {
    return (uint32_t)__cvta_generic_to_shared(p);
}

#define CP16(dst_s32, src_gen) \
    asm volatile("cp.async.cg.shared.global [%0], [%1], 16;" :: "r"(dst_s32), "l"(src_gen))
#define CP_COMMIT()  asm volatile("cp.async.commit_group;")
#define CP_WAIT0()   asm volatile("cp.async.wait_group 0;")

// ---------------------------------------------------------------------------
// tf32 tensor-core GEMM (R7-validated): C[m,n] = sum_k A[m,k]*B[n,k], f32 out
// ---------------------------------------------------------------------------
__global__ void __launch_bounds__(256)
gemm_tf32_nt(const float* __restrict__ A, const float* __restrict__ Bm,
             float* __restrict__ C, int K, int N) {
    __shared__ uint32_t As[2][128][20];
    __shared__ uint32_t Bs[2][128][20];

    const int tid  = threadIdx.x;
    const int lrow = tid >> 1;
    const int lcol = (tid & 1) * 8;

    const int m0g = blockIdx.y * 128;
    const int n0g = blockIdx.x * 128;

    const float* Ag = A  + (size_t)(m0g + lrow) * K + lcol;
    const float* Bg = Bm + (size_t)(n0g + lrow) * K + lcol;

    const int w    = tid >> 5;
    const int lane = tid & 31;
    const int g = lane >> 2;
    const int t = lane & 3;
    const int wm = (w >> 1) * 32;
    const int wn = (w & 1) * 64;

    float acc[2][8][4];
#pragma unroll
    for (int mi = 0; mi < 2; mi++)
#pragma unroll
        for (int ni = 0; ni < 8; ni++)
#pragma unroll
            for (int r = 0; r < 4; r++) acc[mi][ni][r] = 0.f;

    float4 pa0, pa1, pb0, pb1;

#define GT_STORE(bufi)                                                          \
    do {                                                                        \
        *(uint4*)&As[bufi][lrow][lcol] =                                        \
            make_uint4(f2tf(pa0.x), f2tf(pa0.y), f2tf(pa0.z), f2tf(pa0.w));     \
        *(uint4*)&As[bufi][lrow][lcol + 4] =                                    \
            make_uint4(f2tf(pa1.x), f2tf(pa1.y), f2tf(pa1.z), f2tf(pa1.w));     \
        *(uint4*)&Bs[bufi][lrow][lcol] =                                        \
            make_uint4(f2tf(pb0.x), f2tf(pb0.y), f2tf(pb0.z), f2tf(pb0.w));     \
        *(uint4*)&Bs[bufi][lrow][lcol + 4] =                                    \
            make_uint4(f2tf(pb1.x), f2tf(pb1.y), f2tf(pb1.z), f2tf(pb1.w));     \
    } while (0)

    pa0 = *(const float4*)(Ag);     pa1 = *(const float4*)(Ag + 4);
    pb0 = *(const float4*)(Bg);     pb1 = *(const float4*)(Bg + 4);
    GT_STORE(0);
    __syncthreads();

    int buf = 0;
    for (int kk = BK; kk <= K; kk += BK) {
        const bool more = (kk < K);
        if (more) {
            pa0 = *(const float4*)(Ag + kk);  pa1 = *(const float4*)(Ag + kk + 4);
            pb0 = *(const float4*)(Bg + kk);  pb1 = *(const float4*)(Bg + kk + 4);
        }
#pragma unroll
        for (int kc = 0; kc < 2; kc++) {
            uint32_t ar[2][4];
#pragma unroll
            for (int mi = 0; mi < 2; mi++) {
                ar[mi][0] = As[buf][wm + mi * 16 + g    ][kc * 8 + t];
                ar[mi][1] = As[buf][wm + mi * 16 + g + 8][kc * 8 + t];
                ar[mi][2] = As[buf][wm + mi * 16 + g    ][kc * 8 + t + 4];
                ar[mi][3] = As[buf][wm + mi * 16 + g + 8][kc * 8 + t + 4];
            }
            uint32_t br[8][2];
#pragma unroll
            for (int ni = 0; ni < 8; ni++) {
                br[ni][0] = Bs[buf][wn + ni * 8 + g][kc * 8 + t];
                br[ni][1] = Bs[buf][wn + ni * 8 + g][kc * 8 + t + 4];
            }
#pragma unroll
            for (int mi = 0; mi < 2; mi++)
#pragma unroll
                for (int ni = 0; ni < 8; ni++)
                    mma_tf32(acc[mi][ni][0], acc[mi][ni][1], acc[mi][ni][2], acc[mi][ni][3],
                             ar[mi][0], ar[mi][1], ar[mi][2], ar[mi][3],
                             br[ni][0], br[ni][1]);
        }
        if (more) {
            GT_STORE(buf ^ 1);
            __syncthreads();
            buf ^= 1;
        }
    }
#undef GT_STORE

#pragma unroll
    for (int mi = 0; mi < 2; mi++) {
        const int row_lo = m0g + wm + mi * 16 + g;
#pragma unroll
        for (int ni = 0; ni < 8; ni++) {
            const int col = n0g + wn + ni * 8 + 2 * t;
            *(float2*)(C + (size_t)row_lo * N + col) =
                make_float2(acc[mi][ni][0], acc[mi][ni][1]);
            *(float2*)(C + (size_t)(row_lo + 8) * N + col) =
                make_float2(acc[mi][ni][2], acc[mi][ni][3]);
        }
    }
}

// ---------------------------------------------------------------------------
// fp32 SGEMM for Q/K projections (precision-critical; unchanged)
// ---------------------------------------------------------------------------
__device__ __forceinline__ void sgemm_tile(const float* __restrict__ A,
                                           const float* __restrict__ Bm,
                                           float* __restrict__ C,
                                           int m0, int n0, int K, int ldc) {
    __shared__ __align__(16) float As[2][BK][128];
    __shared__ __align__(16) float Bs[2][BK][128];

    const int tid  = threadIdx.x;
    const int lrow = tid >> 1;
    const int lcol = (tid & 1) * 8;

    const float* Ag = A  + (size_t)(m0 + lrow) * K + lcol;
    const float* Bg = Bm + (size_t)(n0 + lrow) * K + lcol;

    const int ty = tid >> 4;
    const int tx = tid & 15;

    float acc[8][8];
#pragma unroll
    for (int i = 0; i < 8; i++)
#pragma unroll
        for (int j = 0; j < 8; j++) acc[i][j] = 0.f;

    float4 a0, a1, b0, b1;

#define QK_STORE_TILE(bufi)                                                     \
    do {                                                                        \
        As[bufi][lcol + 0][lrow] = a0.x; As[bufi][lcol + 1][lrow] = a0.y;       \
        As[bufi][lcol + 2][lrow] = a0.z; As[bufi][lcol + 3][lrow] = a0.w;       \
        As[bufi][lcol + 4][lrow] = a1.x; As[bufi][lcol + 5][lrow] = a1.y;       \
        As[bufi][lcol + 6][lrow] = a1.z; As[bufi][lcol + 7][lrow] = a1.w;       \
        Bs[bufi][lcol + 0][lrow] = b0.x; Bs[bufi][lcol + 1][lrow] = b0.y;       \
        Bs[bufi][lcol + 2][lrow] = b0.z; Bs[bufi][lcol + 3][lrow] = b0.w;       \
        Bs[bufi][lcol + 4][lrow] = b1.x; Bs[bufi][lcol + 5][lrow] = b1.y;       \
        Bs[bufi][lcol + 6][lrow] = b1.z; Bs[bufi][lcol + 7][lrow] = b1.w;       \
    } while (0)

    a0 = *(const float4*)(Ag);     a1 = *(const float4*)(Ag + 4);
    b0 = *(const float4*)(Bg);     b1 = *(const float4*)(Bg + 4);
    QK_STORE_TILE(0);
    __syncthreads();

    int buf = 0;
    for (int kk = BK; kk <= K; kk += BK) {
        const bool more = (kk < K);
        if (more) {
            a0 = *(const float4*)(Ag + kk);  a1 = *(const float4*)(Ag + kk + 4);
            b0 = *(const float4*)(Bg + kk);  b1 = *(const float4*)(Bg + kk + 4);
        }
#pragma unroll
        for (int k = 0; k < BK; k++) {
            float a[8], b[8];
            float4 ra0 = *(const float4*)&As[buf][k][ty * 8];
            float4 ra1 = *(const float4*)&As[buf][k][ty * 8 + 4];
            float4 rb0 = *(const float4*)&Bs[buf][k][tx * 8];
            float4 rb1 = *(const float4*)&Bs[buf][k][tx * 8 + 4];
            a[0]=ra0.x; a[1]=ra0.y; a[2]=ra0.z; a[3]=ra0.w;
            a[4]=ra1.x; a[5]=ra1.y; a[6]=ra1.z; a[7]=ra1.w;
            b[0]=rb0.x; b[1]=rb0.y; b[2]=rb0.z; b[3]=rb0.w;
            b[4]=rb1.x; b[5]=rb1.y; b[6]=rb1.z; b[7]=rb1.w;
#pragma unroll
            for (int i = 0; i < 8; i++)
#pragma unroll
                for (int j = 0; j < 8; j++) acc[i][j] += a[i] * b[j];
        }
        if (more) {
            QK_STORE_TILE(buf ^ 1);
            __syncthreads();
            buf ^= 1;
        }
    }
#undef QK_STORE_TILE

#pragma unroll
    for (int i = 0; i < 8; i++) {
        float* crow = C + (size_t)(m0 + ty * 8 + i) * ldc + n0 + tx * 8;
        *(float4*)(crow)     = make_float4(acc[i][0], acc[i][1], acc[i][2], acc[i][3]);
        *(float4*)(crow + 4) = make_float4(acc[i][4], acc[i][5], acc[i][6], acc[i][7]);
    }
}

__global__ void __launch_bounds__(256)
sgemm_qk(const float* __restrict__ x,
         const float* __restrict__ Wq, const float* __restrict__ Wk,
         float* __restrict__ q, float* __restrict__ k) {
    const int bx = blockIdx.x;
    const float* Bm = (bx < 2) ? Wq : Wk;
    float* C        = (bx < 2) ? q  : k;
    const int n0 = (bx & 1) * 128;
    sgemm_tile(x, Bm, C, blockIdx.y * 128, n0, HID, NH * FDIM);
}

// ---------------------------------------------------------------------------
// Feature map on q and k; outputs tf32-RNA-rounded (raw bits feed stage-1 MMA
// directly — path bit-validated in R11).
// ---------------------------------------------------------------------------
__global__ void featmap2(float* __restrict__ q, float* __restrict__ k,
                         const float* __restrict__ gamma,
                         const float* __restrict__ beta, int nrows) {
    int i = blockIdx.x * blockDim.x + threadIdx.x;
    float scale;
    float* t;
    if (i < nrows)          { t = q; scale = 0.25f; }
    else if (i < 2 * nrows) { t = k; scale = 1.0f; i -= nrows; }
    else return;

    float* p = t + (size_t)i * 16;
    float v[16];
    float4* p4 = (float4*)p;
#pragma unroll
    for (int c = 0; c < 4; c++) {
        float4 f = p4[c];
        v[4 * c + 0] = f.x; v[4 * c + 1] = f.y; v[4 * c + 2] = f.z; v[4 * c + 3] = f.w;
    }
    float mu = 0.f;
#pragma unroll
    for (int d = 0; d < 16; d++) mu += v[d];
    mu *= (1.f / 16.f);
    float var = 0.f;
#pragma unroll
    for (int d = 0; d < 16; d++) { float dd = v[d] - mu; var += dd * dd; }
    var *= (1.f / 16.f);
    float r = rsqrtf(var + 1e-5f);
#pragma unroll
    for (int d = 0; d < 16; d++)
        v[d] = ((v[d] - mu) * r * __ldg(&gamma[d]) + __ldg(&beta[d])) * scale;
    uint4* pu = (uint4*)p;
#pragma unroll
    for (int c = 0; c < 4; c++)
        pu[c] = make_uint4(f2tf(v[4 * c]), f2tf(v[4 * c + 1]),
                           f2tf(v[4 * c + 2]), f2tf(v[4 * c + 3]));
}

// ---------------------------------------------------------------------------
// Tensor-core causal quadratic attention v6 (FA-style f16 stage 3):
//  - stage1: tf32 m16n8k8, K tile cp.async'd pre-rounded straight into the
//    padded layout (double-buffered) — bit-identical path from R11.
//  - stage2: mask/square/z in fp32, pack S into f16x2 A-frags IN REGISTERS
//    (m16n8k16 A-frag == two adjacent m16n8k8 C-frags; no shfl, no smem).
//  - stage3: f16 m16n8k16 (2x-rate pipe, half the MMA count), V converted to
//    f16 TRANSPOSED [hd][key] by the per-tile convert pass (v4-style staging).
//  - q frags via direct LDG (no qs smem). smem 35 KB.
// ---------------------------------------------------------------------------
__global__ void __launch_bounds__(256)
attn_mma(const float* __restrict__ q, const float* __restrict__ k,
         const float* __restrict__ v, float* __restrict__ o_) {
    __shared__ __align__(16) uint32_t pool[8768];   // 35 KB
    // [0:2560)      ks[2]: [64][20] tf32 (double-buffered, direct cp.async)
    // [2560:6656)   raw_v: [64][64] fp32 staging
    // [6656:8768)   vsT:   [64 hd][33 words] f16x2, word kp = keys {2kp,2kp+1}
    uint32_t* const raw_v = pool + 2560;
    uint32_t* const vsT   = pool + 6656;

    const int bh = blockIdx.y;
    const int b = bh >> 4;
    const int h = bh & 15;
    const int qt = gridDim.x - 1 - blockIdx.x;   // heavy blocks first (128-row tile)
    const int tid = threadIdx.x;
    const int lane = tid & 31;
    const int w = tid >> 5;
    const int wl = w & 3;                  // warp index within group
    const int isB = w >> 2;                // 0: q rows [0,64), 1: [64,128)
    const int goff = isB * 64;
    const int g = lane >> 2;
    const int t = lane & 3;

    // ---- Q fragments via direct LDG (q pre-rounded tf32; raw bits)
    uint32_t qa[2][4];
    {
        const uint32_t* qbits = (const uint32_t*)q;
        const int r0 = qt * 128 + goff + wl * 16 + g;
        const size_t base_lo = (size_t)(b * LL + r0) * (NH * FDIM) + h * FDIM;
        const size_t base_hi = base_lo + (size_t)8 * (NH * FDIM);
#pragma unroll
        for (int kc = 0; kc < 2; kc++) {
            qa[kc][0] = qbits[base_lo + kc * 8 + t];
            qa[kc][1] = qbits[base_hi + kc * 8 + t];
            qa[kc][2] = qbits[base_lo + kc * 8 + t + 4];
            qa[kc][3] = qbits[base_hi + kc * 8 + t + 4];
        }
    }

    const float* kbase = k + (size_t)(b * LL) * (NH * FDIM) + h * FDIM;  // row stride 256
    const float* vbase = v + (size_t)(b * LL) * HID + h * HDIM;          // row stride 1024

    // cp.async one 64-key tile: k direct into ks[bi] padded layout, v into staging
    auto issue_tile = [&](int kt, int bi) {
        uint32_t* const ksd = pool + bi * 1280;
        const float* kb = kbase + (size_t)(kt * 64) * (NH * FDIM);
        const float* vb = vbase + (size_t)(kt * 64) * HID;
        {
            const int row = tid >> 2, quad = tid & 3;
            CP16(sptr(ksd + row * 20 + quad * 4), kb + row * 256 + quad * 4);
        }
#pragma unroll
        for (int i = 0; i < 4; i++) {
            const int c = tid + 256 * i;
            const int row = c >> 4, quad = c & 15;
            CP16(sptr(raw_v + row * 64 + quad * 4), vb + row * 1024 + quad * 4);
        }
        CP_COMMIT();
    };

    issue_tile(0, 0);

    float oc[8][4];
#pragma unroll
    for (int nt = 0; nt < 8; nt++)
#pragma unroll
        for (int r = 0; r < 4; r++) oc[nt][r] = 0.f;
    float z_lo = 0.f, z_hi = 0.f;

    const int last_kt = 2 * qt + 1;
    const int my_diag = 2 * qt + isB;      // this group's diagonal key tile

    // convert-pass thread mapping: hd = tid&63, kp group = tid>>6 (8 kps each)
    const int cv_hd = tid & 63;
    const int cv_kp0 = (tid >> 6) * 8;

    for (int kt = 0; kt <= last_kt; kt++) {
        const int cur = kt & 1;
        CP_WAIT0();
        __syncthreads();   // tile kt landed; all prev MMAs done (vsT/ks[nxt] free)

        // ---- convert V: fp32 [key][hd] -> f16x2 transposed [hd][keypair]
#pragma unroll
        for (int j = 0; j < 8; j++) {
            const int kp = cv_kp0 + j;
            const float f0 = __uint_as_float(raw_v[(2 * kp    ) * 64 + cv_hd]);
            const float f1 = __uint_as_float(raw_v[(2 * kp + 1) * 64 + cv_hd]);
            vsT[cv_hd * 33 + kp] = pack_h2(f0, f1);
        }
        __syncthreads();   // vsT ready; raw_v free for next tile

        if (kt < last_kt) issue_tile(kt + 1, cur ^ 1);   // overlaps MMA stages

        if (kt > my_diag) continue;   // group A idles on the final tile

        const uint32_t* ks = pool + cur * 1280;

        // ---- stage 1: S = Q K^T (tf32)
        float sc[8][4];
#pragma unroll
        for (int nt = 0; nt < 8; nt++) {
            sc[nt][0] = sc[nt][1] = sc[nt][2] = sc[nt][3] = 0.f;
#pragma unroll
            for (int kc = 0; kc < 2; kc++) {
                uint32_t b0 = ks[(nt * 8 + g) * 20 + kc * 8 + t];
                uint32_t b1 = ks[(nt * 8 + g) * 20 + kc * 8 + t + 4];
                mma_tf32(sc[nt][0], sc[nt][1], sc[nt][2], sc[nt][3],
                         qa[kc][0], qa[kc][1], qa[kc][2], qa[kc][3], b0, b1);
            }
        }

        // ---- stage 2: causal mask (diag tile), square, z accum, pack f16 A-frags
        const bool diag = (kt == my_diag);
        const int rlo = wl * 16 + g;      // row within this group's 64 rows
        const int rhi = rlo + 8;
        uint32_t af[4][4];                // A-frags for m16n8k16 (4 key chunks)
#pragma unroll
        for (int nt = 0; nt < 8; nt++) {
            const int c0col = nt * 8 + 2 * t;
            float s0 = sc[nt][0], s1 = sc[nt][1], s2 = sc[nt][2], s3 = sc[nt][3];
            if (diag) {
                if (c0col     > rlo) s0 = 0.f;
                if (c0col + 1 > rlo) s1 = 0.f;
                if (c0col     > rhi) s2 = 0.f;
                if (c0col + 1 > rhi) s3 = 0.f;
            }
            s0 *= s0; s1 *= s1; s2 *= s2; s3 *= s3;
            z_lo += s0 + s1;
            z_hi += s2 + s3;
            // m16n8k16 A-frag identity: even nt -> regs {0,1}, odd nt -> {2,3}
            af[nt >> 1][(nt & 1) * 2 + 0] = pack_h2(s0, s1);
            af[nt >> 1][(nt & 1) * 2 + 1] = pack_h2(s2, s3);
        }

        // ---- stage 3: O += S V  (f16 m16n8k16; B from transposed f16 V)
#pragma unroll
        for (int kc = 0; kc < 4; kc++) {
#pragma unroll
            for (int nt = 0; nt < 8; nt++) {
                const uint32_t vb0 = vsT[(nt * 8 + g) * 33 + kc * 8 + t];
                const uint32_t vb1 = vsT[(nt * 8 + g) * 33 + kc * 8 + t + 4];
                mma_f16(oc[nt][0], oc[nt][1], oc[nt][2], oc[nt][3],
                        af[kc][0], af[kc][1], af[kc][2], af[kc][3], vb0, vb1);
            }
        }
    }

    // ---- epilogue: z reduce over the 4 lanes of each row quad, normalize, store
    z_lo += __shfl_xor_sync(0xffffffffu, z_lo, 1);
    z_lo += __shfl_xor_sync(0xffffffffu, z_lo, 2);
    z_hi += __shfl_xor_sync(0xffffffffu, z_hi, 1);
    z_hi += __shfl_xor_sync(0xffffffffu, z_hi, 2);
    const float inv_lo = 1.f / (z_lo + 1e-5f);
    const float inv_hi = 1.f / (z_hi + 1e-5f);

    const int qrow_lo = qt * 128 + goff + wl * 16 + g;
    float* obase = o_ + (size_t)(b * LL) * HID + h * HDIM;
#pragma unroll
    for (int nt = 0; nt < 8; nt++) {
        const int col = nt * 8 + 2 * t;
        *(float2*)(obase + (size_t)qrow_lo * HID + col) =
            make_float2(oc[nt][0] * inv_lo, oc[nt][1] * inv_lo);
        *(float2*)(obase + (size_t)(qrow_lo + 8) * HID + col) =
            make_float2(oc[nt][2] * inv_hi, oc[nt][3] * inv_hi);
    }
}

// ---------------------------------------------------------------------------
extern "C" void kernel_launch(void* const* d_in, const int* in_sizes, int n_in,
                              void* d_out, int out_size) {
    const float* x     = (const float*)d_in[0];   // (2,2048,1024)
    const float* Wq    = (const float*)d_in[1];   // (256,1024)
    const float* Wk    = (const float*)d_in[2];   // (256,1024)
    const float* Wv    = (const float*)d_in[3];   // (1024,1024)
    const float* Wo    = (const float*)d_in[4];   // (1024,1024)
    const float* gamma = (const float*)d_in[5];   // (16,)
    const float* beta  = (const float*)d_in[6];   // (16,)
    float* out = (float*)d_out;

    float *q, *k, *v, *o;
    cudaGetSymbolAddress((void**)&q, g_q);
    cudaGetSymbolAddress((void**)&k, g_k);
    cudaGetSymbolAddress((void**)&v, g_v);
    cudaGetSymbolAddress((void**)&o, g_o);

    // Q/K projection: fp32 (precision-critical due to downstream squaring)
    sgemm_qk<<<dim3(4, 32), 256>>>(x, Wq, Wk, q, k);
    // V projection: tf32 tensor cores, f32 output (converted to f16 in attn)
    gemm_tf32_nt<<<dim3(HID / 128, MTOT / 128), 256>>>(x, Wv, v, HID, HID);

    // Feature maps for q (scale FD^-0.5=0.25) and k; outputs tf32-rounded
    const int nrows = MTOT * NH;
    featmap2<<<(2 * nrows + 255) / 256, 256>>>(q, k, gamma, beta, nrows);

    // Tensor-core causal quadratic attention (f16 stage-3, pipelined)
    attn_mma<<<dim3(LL / 128, BB * NH), 256>>>(q, k, v, o);

    // Output projection: tf32 tensor cores
    gemm_tf32_nt<<<dim3(HID / 128, MTOT / 128), 256>>>(o, Wo, out, HID, HID);
}

// round 13
// speedup vs baseline: 1.1361x; 1.1361x over previous
#include <cuda_runtime.h>
#include <cstdint>

#define BB 2
#define LL 2048
#define HID 1024
#define NH 16
#define FDIM 16
#define HDIM 64
#define MTOT (BB*LL)   // 4096
#define BK 16

// Scratch (static __device__ — no allocation allowed)
__device__ float g_q[MTOT * NH * FDIM];   // 4 MB
__device__ float g_k[MTOT * NH * FDIM];   // 4 MB
__device__ float g_v[MTOT * HID];         // 16 MB
__device__ float g_o[MTOT * HID];         // 16 MB

// ---------------------------------------------------------------------------
// tf32 helpers (fragment layouts validated in R6/R7)
// ---------------------------------------------------------------------------
__device__ __forceinline__ void mma_tf32(float& d0, float& d1, float& d2, float& d3,
                                         uint32_t a0, uint32_t a1, uint32_t a2, uint32_t a3,
                                         uint32_t b0, uint32_t b1) {
    asm volatile("mma.sync.aligned.m16n8k8.row.col.f32.tf32.tf32.f32 "
                 "{%0,%1,%2,%3}, {%4,%5,%6,%7}, {%8,%9}, {%0,%1,%2,%3};"
                 : "+f"(d0), "+f"(d1), "+f"(d2), "+f"(d3)
                 : "r"(a0), "r"(a1), "r"(a2), "r"(a3), "r"(b0), "r"(b1));
}

__device__ __forceinline__ uint32_t f2tf(float f) {
    uint32_t u;
    asm("cvt.rna.tf32.f32 %0, %1;" : "=r"(u) : "f"(f));
    return u;
}

__device__ __forceinline__ uint32_t sptr(const void* p) {
    return (uint32_t)__cvta_generic_to_shared(p);
}

#define CP16(dst_s32, src_gen) \
    asm volatile("cp.async.cg.shared.global [%0], [%1], 16;" :: "r"(dst_s32), "l"(src_gen))
#define CP_COMMIT()  asm volatile("cp.async.commit_group;")
#define CP_WAIT0()   asm volatile("cp.async.wait_group 0;")

// ---------------------------------------------------------------------------
// tf32 tensor-core GEMM tile: C[m,n] = sum_k A[m,k]*B[n,k]
// A: MxK row-major, B: NxK row-major. 128x128 CTA tile, 8 warps of 32x64,
// BK=16 double-buffered smem (stride-20 pad = conflict-free frag LDS).
// ---------------------------------------------------------------------------
__device__ __forceinline__ void gemm_tf32_tile(const float* __restrict__ A,
                                               const float* __restrict__ Bm,
                                               float* __restrict__ C,
                                               int m0g, int n0g, int K, int ldc) {
    __shared__ uint32_t As[2][128][20];
    __shared__ uint32_t Bs[2][128][20];

    const int tid  = threadIdx.x;
    const int lrow = tid >> 1;
    const int lcol = (tid & 1) * 8;

    const float* Ag = A  + (size_t)(m0g + lrow) * K + lcol;
    const float* Bg = Bm + (size_t)(n0g + lrow) * K + lcol;

    const int w    = tid >> 5;
    const int lane = tid & 31;
    const int g = lane >> 2;
    const int t = lane & 3;
    const int wm = (w >> 1) * 32;
    const int wn = (w & 1) * 64;

    float acc[2][8][4];
#pragma unroll
    for (int mi = 0; mi < 2; mi++)
#pragma unroll
        for (int ni = 0; ni < 8; ni++)
#pragma unroll
            for (int r = 0; r < 4; r++) acc[mi][ni][r] = 0.f;

    float4 pa0, pa1, pb0, pb1;

#define GT_STORE(bufi)                                                          \
    do {                                                                        \
        *(uint4*)&As[bufi][lrow][lcol] =                                        \
            make_uint4(f2tf(pa0.x), f2tf(pa0.y), f2tf(pa0.z), f2tf(pa0.w));     \
        *(uint4*)&As[bufi][lrow][lcol + 4] =                                    \
            make_uint4(f2tf(pa1.x), f2tf(pa1.y), f2tf(pa1.z), f2tf(pa1.w));     \
        *(uint4*)&Bs[bufi][lrow][lcol] =                                        \
            make_uint4(f2tf(pb0.x), f2tf(pb0.y), f2tf(pb0.z), f2tf(pb0.w));     \
        *(uint4*)&Bs[bufi][lrow][lcol + 4] =                                    \
            make_uint4(f2tf(pb1.x), f2tf(pb1.y), f2tf(pb1.z), f2tf(pb1.w));     \
    } while (0)

    pa0 = *(const float4*)(Ag);     pa1 = *(const float4*)(Ag + 4);
    pb0 = *(const float4*)(Bg);     pb1 = *(const float4*)(Bg + 4);
    GT_STORE(0);
    __syncthreads();

    int buf = 0;
    for (int kk = BK; kk <= K; kk += BK) {
        const bool more = (kk < K);
        if (more) {
            pa0 = *(const float4*)(Ag + kk);  pa1 = *(const float4*)(Ag + kk + 4);
            pb0 = *(const float4*)(Bg + kk);  pb1 = *(const float4*)(Bg + kk + 4);
        }
#pragma unroll
        for (int kc = 0; kc < 2; kc++) {
            uint32_t ar[2][4];
#pragma unroll
            for (int mi = 0; mi < 2; mi++) {
                ar[mi][0] = As[buf][wm + mi * 16 + g    ][kc * 8 + t];
                ar[mi][1] = As[buf][wm + mi * 16 + g + 8][kc * 8 + t];
                ar[mi][2] = As[buf][wm + mi * 16 + g    ][kc * 8 + t + 4];
                ar[mi][3] = As[buf][wm + mi * 16 + g + 8][kc * 8 + t + 4];
            }
            uint32_t br[8][2];
#pragma unroll
            for (int ni = 0; ni < 8; ni++) {
                br[ni][0] = Bs[buf][wn + ni * 8 + g][kc * 8 + t];
                br[ni][1] = Bs[buf][wn + ni * 8 + g][kc * 8 + t + 4];
            }
#pragma unroll
            for (int mi = 0; mi < 2; mi++)
#pragma unroll
                for (int ni = 0; ni < 8; ni++)
                    mma_tf32(acc[mi][ni][0], acc[mi][ni][1], acc[mi][ni][2], acc[mi][ni][3],
                             ar[mi][0], ar[mi][1], ar[mi][2], ar[mi][3],
                             br[ni][0], br[ni][1]);
        }
        if (more) {
            GT_STORE(buf ^ 1);
            __syncthreads();
            buf ^= 1;
        }
    }
#undef GT_STORE

#pragma unroll
    for (int mi = 0; mi < 2; mi++) {
        const int row_lo = m0g + wm + mi * 16 + g;
#pragma unroll
        for (int ni = 0; ni < 8; ni++) {
            const int col = n0g + wn + ni * 8 + 2 * t;
            *(float2*)(C + (size_t)row_lo * ldc + col) =
                make_float2(acc[mi][ni][0], acc[mi][ni][1]);
            *(float2*)(C + (size_t)(row_lo + 8) * ldc + col) =
                make_float2(acc[mi][ni][2], acc[mi][ni][3]);
        }
    }
}

// V / O projections: N x K, both 128-multiples
__global__ void __launch_bounds__(256)
gemm_tf32_nt(const float* __restrict__ A, const float* __restrict__ Bm,
             float* __restrict__ C, int K, int N) {
    gemm_tf32_tile(A, Bm, C, blockIdx.y * 128, blockIdx.x * 128, K, N);
}

// Fused Q+K projection (tf32): 4 x-blocks (2 for Wq->q, 2 for Wk->k), one wave
__global__ void __launch_bounds__(256)
gemm_tf32_qk(const float* __restrict__ x,
             const float* __restrict__ Wq, const float* __restrict__ Wk,
             float* __restrict__ q, float* __restrict__ k) {
    const int bx = blockIdx.x;
    const float* Bm = (bx < 2) ? Wq : Wk;
    float* C        = (bx < 2) ? q  : k;
    const int n0 = (bx & 1) * 128;
    gemm_tf32_tile(x, Bm, C, blockIdx.y * 128, n0, HID, NH * FDIM);
}

// ---------------------------------------------------------------------------
// Feature map on q and k in one launch (plain fp32 output; attn converts).
// ---------------------------------------------------------------------------
__global__ void featmap2(float* __restrict__ q, float* __restrict__ k,
                         const float* __restrict__ gamma,
                         const float* __restrict__ beta, int nrows) {
    int i = blockIdx.x * blockDim.x + threadIdx.x;
    float scale;
    float* t;
    if (i < nrows)          { t = q; scale = 0.25f; }
    else if (i < 2 * nrows) { t = k; scale = 1.0f; i -= nrows; }
    else return;

    float* p = t + (size_t)i * 16;
    float v[16];
    float4* p4 = (float4*)p;
#pragma unroll
    for (int c = 0; c < 4; c++) {
        float4 f = p4[c];
        v[4 * c + 0] = f.x; v[4 * c + 1] = f.y; v[4 * c + 2] = f.z; v[4 * c + 3] = f.w;
    }
    float mu = 0.f;
#pragma unroll
    for (int d = 0; d < 16; d++) mu += v[d];
    mu *= (1.f / 16.f);
    float var = 0.f;
#pragma unroll
    for (int d = 0; d < 16; d++) { float dd = v[d] - mu; var += dd * dd; }
    var *= (1.f / 16.f);
    float r = rsqrtf(var + 1e-5f);
#pragma unroll
    for (int d = 0; d < 16; d++)
        v[d] = ((v[d] - mu) * r * __ldg(&gamma[d]) + __ldg(&beta[d])) * scale;
#pragma unroll
    for (int c = 0; c < 4; c++)
        p4[c] = make_float4(v[4 * c], v[4 * c + 1], v[4 * c + 2], v[4 * c + 3]);
}

// ---------------------------------------------------------------------------
// Tensor-core causal quadratic attention v4 (R10, measured 141 us — best):
//  - 128 q-rows per block (8 warps); warps 0-3 own q rows [0,64), 4-7 own
//    [64,128). 64-key tiles cp.async'd into fp32 staging one iter ahead,
//    then converted to padded tf32 tiles; fixed costs amortized over 2x MMAs.
//  - Group A diag = key-tile 2qt, group B = 2qt+1; A idles on the last tile.
// ---------------------------------------------------------------------------
__global__ void __launch_bounds__(256)
attn_mma(const float* __restrict__ q, const float* __restrict__ k,
         const float* __restrict__ v, float* __restrict__ o_) {
    __shared__ __align__(16) uint32_t pool[11008];   // 43 KB
    uint32_t* const raw_k = pool;          // [64][16] raw fp32 bits
    uint32_t* const raw_v = pool + 1024;   // [64][64] raw fp32 bits
    uint32_t* const qs    = pool;          // [128][20] (aliases staging; once)
    uint32_t* const ks    = pool + 5120;   // [64][20] tf32
    uint32_t* const vs    = pool + 6400;   // [64][72] tf32

    const int bh = blockIdx.y;
    const int b = bh >> 4;
    const int h = bh & 15;
    const int qt = gridDim.x - 1 - blockIdx.x;   // heavy blocks first (128-row tile)
    const int tid = threadIdx.x;
    const int lane = tid & 31;
    const int w = tid >> 5;
    const int wl = w & 3;                  // warp index within group
    const int isB = w >> 2;                // 0: q rows [0,64), 1: [64,128)
    const int goff = isB * 64;
    const int g = lane >> 2;
    const int t = lane & 3;

    // ---- fill qs (once): 128 rows x 16 fd, tf32; then extract frags, release
    {
        const int row = tid >> 1, c0 = (tid & 1) * 8;
        const float* src = q + (size_t)(b * LL + qt * 128 + row) * (NH * FDIM) + h * FDIM + c0;
        float4 f0 = ((const float4*)src)[0];
        float4 f1 = ((const float4*)src)[1];
        *(uint4*)(qs + row * 20 + c0) =
            make_uint4(f2tf(f0.x), f2tf(f0.y), f2tf(f0.z), f2tf(f0.w));
        *(uint4*)(qs + row * 20 + c0 + 4) =
            make_uint4(f2tf(f1.x), f2tf(f1.y), f2tf(f1.z), f2tf(f1.w));
    }
    __syncthreads();

    uint32_t qa[2][4];
#pragma unroll
    for (int kc = 0; kc < 2; kc++) {
        const int r0 = goff + wl * 16;
        qa[kc][0] = qs[(r0 + g    ) * 20 + kc * 8 + t];
        qa[kc][1] = qs[(r0 + g + 8) * 20 + kc * 8 + t];
        qa[kc][2] = qs[(r0 + g    ) * 20 + kc * 8 + t + 4];
        qa[kc][3] = qs[(r0 + g + 8) * 20 + kc * 8 + t + 4];
    }
    __syncthreads();   // all reads of qs done -> staging region free

    const float* kbase = k + (size_t)(b * LL) * (NH * FDIM) + h * FDIM;  // row stride 256
    const float* vbase = v + (size_t)(b * LL) * HID + h * HDIM;          // row stride 1024

    // cp.async one 64-key tile (k: 256 16B-chunks, v: 1024 16B-chunks; 256 thr)
    auto issue_tile = [&](int kt) {
        const float* kb = kbase + (size_t)(kt * 64) * (NH * FDIM);
        const float* vb = vbase + (size_t)(kt * 64) * HID;
        {
            const int row = tid >> 2, quad = tid & 3;
            CP16(sptr(raw_k + row * 16 + quad * 4), kb + row * 256 + quad * 4);
        }
#pragma unroll
        for (int i = 0; i < 4; i++) {
            const int c = tid + 256 * i;
            const int row = c >> 4, quad = c & 15;
            CP16(sptr(raw_v + row * 64 + quad * 4), vb + row * 1024 + quad * 4);
        }
        CP_COMMIT();
    };

    issue_tile(0);

    float oc[8][4];
#pragma unroll
    for (int nt = 0; nt < 8; nt++)
#pragma unroll
        for (int r = 0; r < 4; r++) oc[nt][r] = 0.f;
    float z_lo = 0.f, z_hi = 0.f;

    const int src1 = (lane & ~3) | (t >> 1);
    const int src2 = src1 | 2;

    const int last_kt = 2 * qt + 1;
    const int my_diag = 2 * qt + isB;      // this group's diagonal key tile

    for (int kt = 0; kt <= last_kt; kt++) {
        CP_WAIT0();
        __syncthreads();   // staging(kt) visible; ks/vs free (prev MMAs done)

        // ---- convert raw fp32 -> tf32 padded tiles (256 threads)
        {
            const int row = tid >> 2, quad = tid & 3;
            float4 f = *(const float4*)(raw_k + row * 16 + quad * 4);
            *(uint4*)(ks + row * 20 + quad * 4) =
                make_uint4(f2tf(f.x), f2tf(f.y), f2tf(f.z), f2tf(f.w));
        }
#pragma unroll
        for (int i = 0; i < 4; i++) {
            const int c = tid + 256 * i;
            const int row = c >> 4, quad = c & 15;
            float4 f = *(const float4*)(raw_v + row * 64 + quad * 4);
            *(uint4*)(vs + row * 72 + quad * 4) =
                make_uint4(f2tf(f.x), f2tf(f.y), f2tf(f.z), f2tf(f.w));
        }
        __syncthreads();   // convert done: staging free, tf32 tiles ready

        if (kt < last_kt) issue_tile(kt + 1);   // overlaps with MMA stages

        if (kt > my_diag) continue;   // group A idles on the final tile

        // ---- stage 1: S = Q K^T
        float sc[8][4];
#pragma unroll
        for (int nt = 0; nt < 8; nt++) {
            sc[nt][0] = sc[nt][1] = sc[nt][2] = sc[nt][3] = 0.f;
#pragma unroll
            for (int kc = 0; kc < 2; kc++) {
                uint32_t b0 = ks[(nt * 8 + g) * 20 + kc * 8 + t];
                uint32_t b1 = ks[(nt * 8 + g) * 20 + kc * 8 + t + 4];
                mma_tf32(sc[nt][0], sc[nt][1], sc[nt][2], sc[nt][3],
                         qa[kc][0], qa[kc][1], qa[kc][2], qa[kc][3], b0, b1);
            }
        }

        // ---- stage 2: causal mask (diag tile), square, z accum, cvt to tf32
        const bool diag = (kt == my_diag);
        const int rlo = wl * 16 + g;      // row within this group's 64 rows
        const int rhi = rlo + 8;
        uint32_t scq[8][4];
#pragma unroll
        for (int nt = 0; nt < 8; nt++) {
            const int c0col = nt * 8 + 2 * t;
            float s0 = sc[nt][0], s1 = sc[nt][1], s2 = sc[nt][2], s3 = sc[nt][3];
            if (diag) {
                if (c0col     > rlo) s0 = 0.f;
                if (c0col + 1 > rlo) s1 = 0.f;
                if (c0col     > rhi) s2 = 0.f;
                if (c0col + 1 > rhi) s3 = 0.f;
            }
            s0 *= s0; s1 *= s1; s2 *= s2; s3 *= s3;
            z_lo += s0 + s1;
            z_hi += s2 + s3;
            scq[nt][0] = f2tf(s0); scq[nt][1] = f2tf(s1);
            scq[nt][2] = f2tf(s2); scq[nt][3] = f2tf(s3);
        }

        // ---- stage 3: O += S V, S relayout via shuffles (C-frag -> A-frag)
#pragma unroll
        for (int kc = 0; kc < 8; kc++) {
            uint32_t u0 = __shfl_sync(0xffffffffu, scq[kc][0], src1);
            uint32_t u1 = __shfl_sync(0xffffffffu, scq[kc][1], src1);
            uint32_t u2 = __shfl_sync(0xffffffffu, scq[kc][2], src1);
            uint32_t u3 = __shfl_sync(0xffffffffu, scq[kc][3], src1);
            uint32_t w0 = __shfl_sync(0xffffffffu, scq[kc][0], src2);
            uint32_t w1 = __shfl_sync(0xffffffffu, scq[kc][1], src2);
            uint32_t w2 = __shfl_sync(0xffffffffu, scq[kc][2], src2);
            uint32_t w3 = __shfl_sync(0xffffffffu, scq[kc][3], src2);
            const bool odd = (t & 1);
            const uint32_t sa0 = odd ? u1 : u0;
            const uint32_t sa1 = odd ? u3 : u2;
            const uint32_t sa2 = odd ? w1 : w0;
            const uint32_t sa3 = odd ? w3 : w2;
#pragma unroll
            for (int nt = 0; nt < 8; nt++) {
                uint32_t vb0 = vs[(kc * 8 + t    ) * 72 + nt * 8 + g];
                uint32_t vb1 = vs[(kc * 8 + t + 4) * 72 + nt * 8 + g];
                mma_tf32(oc[nt][0], oc[nt][1], oc[nt][2], oc[nt][3],
                         sa0, sa1, sa2, sa3, vb0, vb1);
            }
        }
    }

    // ---- epilogue: z reduce over the 4 lanes of each row quad, normalize, store
    z_lo += __shfl_xor_sync(0xffffffffu, z_lo, 1);
    z_lo += __shfl_xor_sync(0xffffffffu, z_lo, 2);
    z_hi += __shfl_xor_sync(0xffffffffu, z_hi, 1);
    z_hi += __shfl_xor_sync(0xffffffffu, z_hi, 2);
    const float inv_lo = 1.f / (z_lo + 1e-5f);
    const float inv_hi = 1.f / (z_hi + 1e-5f);

    const int qrow_lo = qt * 128 + goff + wl * 16 + g;
    float* obase = o_ + (size_t)(b * LL) * HID + h * HDIM;
#pragma unroll
    for (int nt = 0; nt < 8; nt++) {
        const int col = nt * 8 + 2 * t;
        *(float2*)(obase + (size_t)qrow_lo * HID + col) =
            make_float2(oc[nt][0] * inv_lo, oc[nt][1] * inv_lo);
        *(float2*)(obase + (size_t)(qrow_lo + 8) * HID + col) =
            make_float2(oc[nt][2] * inv_hi, oc[nt][3] * inv_hi);
    }
}

// ---------------------------------------------------------------------------
extern "C" void kernel_launch(void* const* d_in, const int* in_sizes, int n_in,
                              void* d_out, int out_size) {
    const float* x     = (const float*)d_in[0];   // (2,2048,1024)
    const float* Wq    = (const float*)d_in[1];   // (256,1024)
    const float* Wk    = (const float*)d_in[2];   // (256,1024)
    const float* Wv    = (const float*)d_in[3];   // (1024,1024)
    const float* Wo    = (const float*)d_in[4];   // (1024,1024)
    const float* gamma = (const float*)d_in[5];   // (16,)
    const float* beta  = (const float*)d_in[6];   // (16,)
    float* out = (float*)d_out;

    float *q, *k, *v, *o;
    cudaGetSymbolAddress((void**)&q, g_q);
    cudaGetSymbolAddress((void**)&k, g_k);
    cudaGetSymbolAddress((void**)&v, g_v);
    cudaGetSymbolAddress((void**)&o, g_o);

    // Q/K projection: tf32 tensor cores (one wave, 128 CTAs)
    gemm_tf32_qk<<<dim3(4, 32), 256>>>(x, Wq, Wk, q, k);
    // V projection: tf32 tensor cores
    gemm_tf32_nt<<<dim3(HID / 128, MTOT / 128), 256>>>(x, Wv, v, HID, HID);

    // Feature maps for q (scale FD^-0.5=0.25) and k
    const int nrows = MTOT * NH;
    featmap2<<<(2 * nrows + 255) / 256, 256>>>(q, k, gamma, beta, nrows);

    // Tensor-core causal quadratic attention (R10 v4 — best measured)
    attn_mma<<<dim3(LL / 128, BB * NH), 256>>>(q, k, v, o);

    // Output projection: tf32 tensor cores
    gemm_tf32_nt<<<dim3(HID / 128, MTOT / 128), 256>>>(o, Wo, out, HID, HID);
}

// round 15
// speedup vs baseline: 1.1487x; 1.0111x over previous
#include <cuda_runtime.h>
#include <cstdint>

#define BB 2
#define LL 2048
#define HID 1024
#define NH 16
#define FDIM 16
#define HDIM 64
#define MTOT (BB*LL)   // 4096
#define BK 16

// Scratch (static __device__ — no allocation allowed)
__device__ float g_q[MTOT * NH * FDIM];   // 4 MB
__device__ float g_k[MTOT * NH * FDIM];   // 4 MB
__device__ float g_v[MTOT * HID];         // 16 MB
__device__ float g_o[MTOT * HID];         // 16 MB

// ---------------------------------------------------------------------------
// tf32 helpers (fragment layouts validated in R6/R7)
// ---------------------------------------------------------------------------
__device__ __forceinline__ void mma_tf32(float& d0, float& d1, float& d2, float& d3,
                                         uint32_t a0, uint32_t a1, uint32_t a2, uint32_t a3,
                                         uint32_t b0, uint32_t b1) {
    asm volatile("mma.sync.aligned.m16n8k8.row.col.f32.tf32.tf32.f32 "
                 "{%0,%1,%2,%3}, {%4,%5,%6,%7}, {%8,%9}, {%0,%1,%2,%3};"
                 : "+f"(d0), "+f"(d1), "+f"(d2), "+f"(d3)
                 : "r"(a0), "r"(a1), "r"(a2), "r"(a3), "r"(b0), "r"(b1));
}

__device__ __forceinline__ uint32_t f2tf(float f) {
    uint32_t u;
    asm("cvt.rna.tf32.f32 %0, %1;" : "=r"(u) : "f"(f));
    return u;
}

__device__ __forceinline__ uint32_t sptr(const void* p) {
    return (uint32_t)__cvta_generic_to_shared(p);
}

#define CP16(dst_s32, src_gen) \
    asm volatile("cp.async.cg.shared.global [%0], [%1], 16;" :: "r"(dst_s32), "l"(src_gen))
#define CP_COMMIT()  asm volatile("cp.async.commit_group;")
#define CP_WAIT0()   asm volatile("cp.async.wait_group 0;")

// ---------------------------------------------------------------------------
// tf32 tensor-core GEMM tile: C[m,n] = sum_k A[m,k]*B[n,k]
// A: MxK row-major, B: NxK row-major. 128x128 CTA tile, 8 warps of 32x64,
// BK=16 double-buffered smem (stride-20 pad = conflict-free frag LDS).
// smem pool passed by caller (40 KB = 10240 words: As[2][128][20], Bs[...]).
// FM=true: fused feature-map epilogue — per 16-col head: layernorm (no
// affine) -> *gamma + beta -> *scale, via quad shfl reductions.
// ---------------------------------------------------------------------------
template <bool FM>
__device__ __forceinline__ void gemm_tf32_tile(uint32_t* __restrict__ smem,
                                               const float* __restrict__ A,
                                               const float* __restrict__ Bm,
                                               float* __restrict__ C,
                                               int m0g, int n0g, int K, int ldc,
                                               const float* __restrict__ gamma,
                                               const float* __restrict__ beta,
                                               float scale) {
    // As buf i at smem + i*2560; Bs buf i at smem + 5120 + i*2560  ([128][20])
    uint32_t* const Asb = smem;
    uint32_t* const Bsb = smem + 5120;

    const int tid  = threadIdx.x;
    const int lrow = tid >> 1;
    const int lcol = (tid & 1) * 8;

    const float* Ag = A  + (size_t)(m0g + lrow) * K + lcol;
    const float* Bg = Bm + (size_t)(n0g + lrow) * K + lcol;

    const int w    = tid >> 5;
    const int lane = tid & 31;
    const int g = lane >> 2;
    const int t = lane & 3;
    const int wm = (w >> 1) * 32;
    const int wn = (w & 1) * 64;

    float acc[2][8][4];
#pragma unroll
    for (int mi = 0; mi < 2; mi++)
#pragma unroll
        for (int ni = 0; ni < 8; ni++)
#pragma unroll
            for (int r = 0; r < 4; r++) acc[mi][ni][r] = 0.f;

    float4 pa0, pa1, pb0, pb1;

#define GT_STORE(bufi)                                                          \
    do {                                                                        \
        *(uint4*)(Asb + (bufi) * 2560 + lrow * 20 + lcol) =                     \
            make_uint4(f2tf(pa0.x), f2tf(pa0.y), f2tf(pa0.z), f2tf(pa0.w));     \
        *(uint4*)(Asb + (bufi) * 2560 + lrow * 20 + lcol + 4) =                 \
            make_uint4(f2tf(pa1.x), f2tf(pa1.y), f2tf(pa1.z), f2tf(pa1.w));     \
        *(uint4*)(Bsb + (bufi) * 2560 + lrow * 20 + lcol) =                     \
            make_uint4(f2tf(pb0.x), f2tf(pb0.y), f2tf(pb0.z), f2tf(pb0.w));     \
        *(uint4*)(Bsb + (bufi) * 2560 + lrow * 20 + lcol + 4) =                 \
            make_uint4(f2tf(pb1.x), f2tf(pb1.y), f2tf(pb1.z), f2tf(pb1.w));     \
    } while (0)

    pa0 = *(const float4*)(Ag);     pa1 = *(const float4*)(Ag + 4);
    pb0 = *(const float4*)(Bg);     pb1 = *(const float4*)(Bg + 4);
    GT_STORE(0);
    __syncthreads();

    int buf = 0;
    for (int kk = BK; kk <= K; kk += BK) {
        const bool more = (kk < K);
        if (more) {
            pa0 = *(const float4*)(Ag + kk);  pa1 = *(const float4*)(Ag + kk + 4);
            pb0 = *(const float4*)(Bg + kk);  pb1 = *(const float4*)(Bg + kk + 4);
        }
        const uint32_t* As = Asb + buf * 2560;
        const uint32_t* Bs = Bsb + buf * 2560;
#pragma unroll
        for (int kc = 0; kc < 2; kc++) {
            uint32_t ar[2][4];
#pragma unroll
            for (int mi = 0; mi < 2; mi++) {
                ar[mi][0] = As[(wm + mi * 16 + g    ) * 20 + kc * 8 + t];
                ar[mi][1] = As[(wm + mi * 16 + g + 8) * 20 + kc * 8 + t];
                ar[mi][2] = As[(wm + mi * 16 + g    ) * 20 + kc * 8 + t + 4];
                ar[mi][3] = As[(wm + mi * 16 + g + 8) * 20 + kc * 8 + t + 4];
            }
            uint32_t br[8][2];
#pragma unroll
            for (int ni = 0; ni < 8; ni++) {
                br[ni][0] = Bs[(wn + ni * 8 + g) * 20 + kc * 8 + t];
                br[ni][1] = Bs[(wn + ni * 8 + g) * 20 + kc * 8 + t + 4];
            }
#pragma unroll
            for (int mi = 0; mi < 2; mi++)
#pragma unroll
                for (int ni = 0; ni < 8; ni++)
                    mma_tf32(acc[mi][ni][0], acc[mi][ni][1], acc[mi][ni][2], acc[mi][ni][3],
                             ar[mi][0], ar[mi][1], ar[mi][2], ar[mi][3],
                             br[ni][0], br[ni][1]);
        }
        if (more) {
            GT_STORE(buf ^ 1);
            __syncthreads();
            buf ^= 1;
        }
    }
#undef GT_STORE

    if (!FM) {
#pragma unroll
        for (int mi = 0; mi < 2; mi++) {
            const int row_lo = m0g + wm + mi * 16 + g;
#pragma unroll
            for (int ni = 0; ni < 8; ni++) {
                const int col = n0g + wn + ni * 8 + 2 * t;
                *(float2*)(C + (size_t)row_lo * ldc + col) =
                    make_float2(acc[mi][ni][0], acc[mi][ni][1]);
                *(float2*)(C + (size_t)(row_lo + 8) * ldc + col) =
                    make_float2(acc[mi][ni][2], acc[mi][ni][3]);
            }
        }
    } else {
        // Fused feature map. For head j (16 cols = nt {2j, 2j+1}), the 16
        // values of one output row live in the 4 lanes of this quad (4 each).
        const float g0 = __ldg(&gamma[2 * t]),     g1 = __ldg(&gamma[2 * t + 1]);
        const float g2 = __ldg(&gamma[8 + 2 * t]), g3 = __ldg(&gamma[8 + 2 * t + 1]);
        const float be0 = __ldg(&beta[2 * t]),     be1 = __ldg(&beta[2 * t + 1]);
        const float be2 = __ldg(&beta[8 + 2 * t]), be3 = __ldg(&beta[8 + 2 * t + 1]);
#pragma unroll
        for (int mi = 0; mi < 2; mi++) {
            const int row_lo = m0g + wm + mi * 16 + g;
#pragma unroll
            for (int j = 0; j < 4; j++) {
                float a0 = acc[mi][2*j][0], a1 = acc[mi][2*j][1];
                float a2 = acc[mi][2*j+1][0], a3 = acc[mi][2*j+1][1];
                float b0 = acc[mi][2*j][2], b1 = acc[mi][2*j][3];
                float b2 = acc[mi][2*j+1][2], b3 = acc[mi][2*j+1][3];
                // mean over 16 (quad reduce)
                float slo = (a0 + a1) + (a2 + a3);
                float shi = (b0 + b1) + (b2 + b3);
                slo += __shfl_xor_sync(0xffffffffu, slo, 1);
                slo += __shfl_xor_sync(0xffffffffu, slo, 2);
                shi += __shfl_xor_sync(0xffffffffu, shi, 1);
                shi += __shfl_xor_sync(0xffffffffu, shi, 2);
                const float mu_lo = slo * (1.f / 16.f);
                const float mu_hi = shi * (1.f / 16.f);
                // centered values + variance (quad reduce)
                a0 -= mu_lo; a1 -= mu_lo; a2 -= mu_lo; a3 -= mu_lo;
                b0 -= mu_hi; b1 -= mu_hi; b2 -= mu_hi; b3 -= mu_hi;
                float vlo = (a0*a0 + a1*a1) + (a2*a2 + a3*a3);
                float vhi = (b0*b0 + b1*b1) + (b2*b2 + b3*b3);
                vlo += __shfl_xor_sync(0xffffffffu, vlo, 1);
                vlo += __shfl_xor_sync(0xffffffffu, vlo, 2);
                vhi += __shfl_xor_sync(0xffffffffu, vhi, 1);
                vhi += __shfl_xor_sync(0xffffffffu, vhi, 2);
                const float r_lo = rsqrtf(vlo * (1.f / 16.f) + 1e-5f);
                const float r_hi = rsqrtf(vhi * (1.f / 16.f) + 1e-5f);
                // normalize, affine, scale, store
                const int col0 = n0g + wn + 16 * j + 2 * t;       // dims 2t,2t+1
                const int col1 = col0 + 8;                        // dims 8+2t,..
                float* rlo = C + (size_t)row_lo * ldc;
                float* rhi = C + (size_t)(row_lo + 8) * ldc;
                *(float2*)(rlo + col0) = make_float2((a0 * r_lo * g0 + be0) * scale,
                                                     (a1 * r_lo * g1 + be1) * scale);
                *(float2*)(rlo + col1) = make_float2((a2 * r_lo * g2 + be2) * scale,
                                                     (a3 * r_lo * g3 + be3) * scale);
                *(float2*)(rhi + col0) = make_float2((b0 * r_hi * g0 + be0) * scale,
                                                     (b1 * r_hi * g1 + be1) * scale);
                *(float2*)(rhi + col1) = make_float2((b2 * r_hi * g2 + be2) * scale,
                                                     (b3 * r_hi * g3 + be3) * scale);
            }
        }
    }
}

// Fused projection kernel: bx 0-1 -> Wq->q (+featmap, scale .25),
// bx 2-3 -> Wk->k (+featmap, scale 1), bx 4-11 -> Wv->v (plain).
// One shared 40 KB pool for all template instantiations.
__global__ void __launch_bounds__(256)
gemm_proj(const float* __restrict__ x,
          const float* __restrict__ Wq, const float* __restrict__ Wk,
          const float* __restrict__ Wv,
          float* __restrict__ q, float* __restrict__ k, float* __restrict__ v,
          const float* __restrict__ gamma, const float* __restrict__ beta) {
    __shared__ __align__(16) uint32_t smem[10240];   // 40 KB
    const int bx = blockIdx.x;
    const int m0 = blockIdx.y * 128;
    if (bx < 2) {
        gemm_tf32_tile<true>(smem, x, Wq, q, m0, bx * 128, HID, NH * FDIM,
                             gamma, beta, 0.25f);
    } else if (bx < 4) {
        gemm_tf32_tile<true>(smem, x, Wk, k, m0, (bx - 2) * 128, HID, NH * FDIM,
                             gamma, beta, 1.0f);
    } else {
        gemm_tf32_tile<false>(smem, x, Wv, v, m0, (bx - 4) * 128, HID, HID,
                              nullptr, nullptr, 1.0f);
    }
}

// O projection: plain tf32 GEMM
__global__ void __launch_bounds__(256)
gemm_tf32_nt(const float* __restrict__ A, const float* __restrict__ Bm,
             float* __restrict__ C, int K, int N) {
    __shared__ __align__(16) uint32_t smem[10240];   // 40 KB
    gemm_tf32_tile<false>(smem, A, Bm, C, blockIdx.y * 128, blockIdx.x * 128,
                          K, N, nullptr, nullptr, 1.0f);
}

// ---------------------------------------------------------------------------
// Tensor-core causal quadratic attention v4 (R10, measured 141-147 us):
//  - 128 q-rows per block (8 warps); 64-key tiles cp.async'd into fp32
//    staging one iter ahead, converted to padded tf32 tiles.
//  - Group A diag = key-tile 2qt, group B = 2qt+1; A idles on the last tile.
// ---------------------------------------------------------------------------
__global__ void __launch_bounds__(256)
attn_mma(const float* __restrict__ q, const float* __restrict__ k,
         const float* __restrict__ v, float* __restrict__ o_) {
    __shared__ __align__(16) uint32_t pool[11008];   // 43 KB
    uint32_t* const raw_k = pool;          // [64][16] raw fp32 bits
    uint32_t* const raw_v = pool + 1024;   // [64][64] raw fp32 bits
    uint32_t* const qs    = pool;          // [128][20] (aliases staging; once)
    uint32_t* const ks    = pool + 5120;   // [64][20] tf32
    uint32_t* const vs    = pool + 6400;   // [64][72] tf32

    const int bh = blockIdx.y;
    const int b = bh >> 4;
    const int h = bh & 15;
    const int qt = gridDim.x - 1 - blockIdx.x;   // heavy blocks first (128-row tile)
    const int tid = threadIdx.x;
    const int lane = tid & 31;
    const int w = tid >> 5;
    const int wl = w & 3;                  // warp index within group
    const int isB = w >> 2;                // 0: q rows [0,64), 1: [64,128)
    const int goff = isB * 64;
    const int g = lane >> 2;
    const int t = lane & 3;

    // ---- fill qs (once): 128 rows x 16 fd, tf32; then extract frags, release
    {
        const int row = tid >> 1, c0 = (tid & 1) * 8;
        const float* src = q + (size_t)(b * LL + qt * 128 + row) * (NH * FDIM) + h * FDIM + c0;
        float4 f0 = ((const float4*)src)[0];
        float4 f1 = ((const float4*)src)[1];
        *(uint4*)(qs + row * 20 + c0) =
            make_uint4(f2tf(f0.x), f2tf(f0.y), f2tf(f0.z), f2tf(f0.w));
        *(uint4*)(qs + row * 20 + c0 + 4) =
            make_uint4(f2tf(f1.x), f2tf(f1.y), f2tf(f1.z), f2tf(f1.w));
    }
    __syncthreads();

    uint32_t qa[2][4];
#pragma unroll
    for (int kc = 0; kc < 2; kc++) {
        const int r0 = goff + wl * 16;
        qa[kc][0] = qs[(r0 + g    ) * 20 + kc * 8 + t];
        qa[kc][1] = qs[(r0 + g + 8) * 20 + kc * 8 + t];
        qa[kc][2] = qs[(r0 + g    ) * 20 + kc * 8 + t + 4];
        qa[kc][3] = qs[(r0 + g + 8) * 20 + kc * 8 + t + 4];
    }
    __syncthreads();   // all reads of qs done -> staging region free

    const float* kbase = k + (size_t)(b * LL) * (NH * FDIM) + h * FDIM;  // row stride 256
    const float* vbase = v + (size_t)(b * LL) * HID + h * HDIM;          // row stride 1024

    // cp.async one 64-key tile (k: 256 16B-chunks, v: 1024 16B-chunks; 256 thr)
    auto issue_tile = [&](int kt) {
        const float* kb = kbase + (size_t)(kt * 64) * (NH * FDIM);
        const float* vb = vbase + (size_t)(kt * 64) * HID;
        {
            const int row = tid >> 2, quad = tid & 3;
            CP16(sptr(raw_k + row * 16 + quad * 4), kb + row * 256 + quad * 4);
        }
#pragma unroll
        for (int i = 0; i < 4; i++) {
            const int c = tid + 256 * i;
            const int row = c >> 4, quad = c & 15;
            CP16(sptr(raw_v + row * 64 + quad * 4), vb + row * 1024 + quad * 4);
        }
        CP_COMMIT();
    };

    issue_tile(0);

    float oc[8][4];
#pragma unroll
    for (int nt = 0; nt < 8; nt++)
#pragma unroll
        for (int r = 0; r < 4; r++) oc[nt][r] = 0.f;
    float z_lo = 0.f, z_hi = 0.f;

    const int src1 = (lane & ~3) | (t >> 1);
    const int src2 = src1 | 2;

    const int last_kt = 2 * qt + 1;
    const int my_diag = 2 * qt + isB;      // this group's diagonal key tile

    for (int kt = 0; kt <= last_kt; kt++) {
        CP_WAIT0();
        __syncthreads();   // staging(kt) visible; ks/vs free (prev MMAs done)

        // ---- convert raw fp32 -> tf32 padded tiles (256 threads)
        {
            const int row = tid >> 2, quad = tid & 3;
            float4 f = *(const float4*)(raw_k + row * 16 + quad * 4);
            *(uint4*)(ks + row * 20 + quad * 4) =
                make_uint4(f2tf(f.x), f2tf(f.y), f2tf(f.z), f2tf(f.w));
        }
#pragma unroll
        for (int i = 0; i < 4; i++) {
            const int c = tid + 256 * i;
            const int row = c >> 4, quad = c & 15;
            float4 f = *(const float4*)(raw_v + row * 64 + quad * 4);
            *(uint4*)(vs + row * 72 + quad * 4) =
                make_uint4(f2tf(f.x), f2tf(f.y), f2tf(f.z), f2tf(f.w));
        }
        __syncthreads();   // convert done: staging free, tf32 tiles ready

        if (kt < last_kt) issue_tile(kt + 1);   // overlaps with MMA stages

        if (kt > my_diag) continue;   // group A idles on the final tile

        // ---- stage 1: S = Q K^T
        float sc[8][4];
#pragma unroll
        for (int nt = 0; nt < 8; nt++) {
            sc[nt][0] = sc[nt][1] = sc[nt][2] = sc[nt][3] = 0.f;
#pragma unroll
            for (int kc = 0; kc < 2; kc++) {
                uint32_t b0 = ks[(nt * 8 + g) * 20 + kc * 8 + t];
                uint32_t b1 = ks[(nt * 8 + g) * 20 + kc * 8 + t + 4];
                mma_tf32(sc[nt][0], sc[nt][1], sc[nt][2], sc[nt][3],
                         qa[kc][0], qa[kc][1], qa[kc][2], qa[kc][3], b0, b1);
            }
        }

        // ---- stage 2: causal mask (diag tile), square, z accum, cvt to tf32
        const bool diag = (kt == my_diag);
        const int rlo = wl * 16 + g;      // row within this group's 64 rows
        const int rhi = rlo + 8;
        uint32_t scq[8][4];
#pragma unroll
        for (int nt = 0; nt < 8; nt++) {
            const int c0col = nt * 8 + 2 * t;
            float s0 = sc[nt][0], s1 = sc[nt][1], s2 = sc[nt][2], s3 = sc[nt][3];
            if (diag) {
                if (c0col     > rlo) s0 = 0.f;
                if (c0col + 1 > rlo) s1 = 0.f;
                if (c0col     > rhi) s2 = 0.f;
                if (c0col + 1 > rhi) s3 = 0.f;
            }
            s0 *= s0; s1 *= s1; s2 *= s2; s3 *= s3;
            z_lo += s0 + s1;
            z_hi += s2 + s3;
            scq[nt][0] = f2tf(s0); scq[nt][1] = f2tf(s1);
            scq[nt][2] = f2tf(s2); scq[nt][3] = f2tf(s3);
        }

        // ---- stage 3: O += S V, S relayout via shuffles (C-frag -> A-frag)
#pragma unroll
        for (int kc = 0; kc < 8; kc++) {
            uint32_t u0 = __shfl_sync(0xffffffffu, scq[kc][0], src1);
            uint32_t u1 = __shfl_sync(0xffffffffu, scq[kc][1], src1);
            uint32_t u2 = __shfl_sync(0xffffffffu, scq[kc][2], src1);
            uint32_t u3 = __shfl_sync(0xffffffffu, scq[kc][3], src1);
            uint32_t w0 = __shfl_sync(0xffffffffu, scq[kc][0], src2);
            uint32_t w1 = __shfl_sync(0xffffffffu, scq[kc][1], src2);
            uint32_t w2 = __shfl_sync(0xffffffffu, scq[kc][2], src2);
            uint32_t w3 = __shfl_sync(0xffffffffu, scq[kc][3], src2);
            const bool odd = (t & 1);
            const uint32_t sa0 = odd ? u1 : u0;
            const uint32_t sa1 = odd ? u3 : u2;
            const uint32_t sa2 = odd ? w1 : w0;
            const uint32_t sa3 = odd ? w3 : w2;
#pragma unroll
            for (int nt = 0; nt < 8; nt++) {
                uint32_t vb0 = vs[(kc * 8 + t    ) * 72 + nt * 8 + g];
                uint32_t vb1 = vs[(kc * 8 + t + 4) * 72 + nt * 8 + g];
                mma_tf32(oc[nt][0], oc[nt][1], oc[nt][2], oc[nt][3],
                         sa0, sa1, sa2, sa3, vb0, vb1);
            }
        }
    }

    // ---- epilogue: z reduce over the 4 lanes of each row quad, normalize, store
    z_lo += __shfl_xor_sync(0xffffffffu, z_lo, 1);
    z_lo += __shfl_xor_sync(0xffffffffu, z_lo, 2);
    z_hi += __shfl_xor_sync(0xffffffffu, z_hi, 1);
    z_hi += __shfl_xor_sync(0xffffffffu, z_hi, 2);
    const float inv_lo = 1.f / (z_lo + 1e-5f);
    const float inv_hi = 1.f / (z_hi + 1e-5f);

    const int qrow_lo = qt * 128 + goff + wl * 16 + g;
    float* obase = o_ + (size_t)(b * LL) * HID + h * HDIM;
#pragma unroll
    for (int nt = 0; nt < 8; nt++) {
        const int col = nt * 8 + 2 * t;
        *(float2*)(obase + (size_t)qrow_lo * HID + col) =
            make_float2(oc[nt][0] * inv_lo, oc[nt][1] * inv_lo);
        *(float2*)(obase + (size_t)(qrow_lo + 8) * HID + col) =
            make_float2(oc[nt][2] * inv_hi, oc[nt][3] * inv_hi);
    }
}

// ---------------------------------------------------------------------------
extern "C" void kernel_launch(void* const* d_in, const int* in_sizes, int n_in,
                              void* d_out, int out_size) {
    const float* x     = (const float*)d_in[0];   // (2,2048,1024)
    const float* Wq    = (const float*)d_in[1];   // (256,1024)
    const float* Wk    = (const float*)d_in[2];   // (256,1024)
    const float* Wv    = (const float*)d_in[3];   // (1024,1024)
    const float* Wo    = (const float*)d_in[4];   // (1024,1024)
    const float* gamma = (const float*)d_in[5];   // (16,)
    const float* beta  = (const float*)d_in[6];   // (16,)
    float* out = (float*)d_out;

    float *q, *k, *v, *o;
    cudaGetSymbolAddress((void**)&q, g_q);
    cudaGetSymbolAddress((void**)&k, g_k);
    cudaGetSymbolAddress((void**)&v, g_v);
    cudaGetSymbolAddress((void**)&o, g_o);

    // Fused Q+K(+featmap) and V projections in ONE launch (384 uniform CTAs)
    gemm_proj<<<dim3(12, 32), 256>>>(x, Wq, Wk, Wv, q, k, v, gamma, beta);

    // Tensor-core causal quadratic attention (R10 v4)
    attn_mma<<<dim3(LL / 128, BB * NH), 256>>>(q, k, v, o);

    // Output projection: tf32 tensor cores
    gemm_tf32_nt<<<dim3(HID / 128, MTOT / 128), 256>>>(o, Wo, out, HID, HID);
}

// round 16
// speedup vs baseline: 1.1674x; 1.0163x over previous
#include <cuda_runtime.h>
#include <cstdint>

#define BB 2
#define LL 2048
#define HID 1024
#define NH 16
#define FDIM 16
#define HDIM 64
#define MTOT (BB*LL)   // 4096

// Scratch (static __device__ — no allocation allowed)
__device__ float g_q[MTOT * NH * FDIM];   // 4 MB
__device__ float g_k[MTOT * NH * FDIM];   // 4 MB
__device__ float g_v[MTOT * HID];         // 16 MB
__device__ float g_o[MTOT * HID];         // 16 MB (tf32-rounded by attn epilogue)
// tf32-rounded copies of GEMM inputs (lets cp.async feed MMA tiles raw)
__device__ float g_xr[MTOT * HID];        // 16 MB
__device__ float g_wqr[NH * FDIM * HID];  // 1 MB
__device__ float g_wkr[NH * FDIM * HID];  // 1 MB
__device__ float g_wvr[HID * HID];        // 4 MB
__device__ float g_wor[HID * HID];        // 4 MB

// ---------------------------------------------------------------------------
// tf32 helpers (fragment layouts validated in R6/R7)
// ---------------------------------------------------------------------------
__device__ __forceinline__ void mma_tf32(float& d0, float& d1, float& d2, float& d3,
                                         uint32_t a0, uint32_t a1, uint32_t a2, uint32_t a3,
                                         uint32_t b0, uint32_t b1) {
    asm volatile("mma.sync.aligned.m16n8k8.row.col.f32.tf32.tf32.f32 "
                 "{%0,%1,%2,%3}, {%4,%5,%6,%7}, {%8,%9}, {%0,%1,%2,%3};"
                 : "+f"(d0), "+f"(d1), "+f"(d2), "+f"(d3)
                 : "r"(a0), "r"(a1), "r"(a2), "r"(a3), "r"(b0), "r"(b1));
}

__device__ __forceinline__ uint32_t f2tf(float f) {
    uint32_t u;
    asm("cvt.rna.tf32.f32 %0, %1;" : "=r"(u) : "f"(f));
    return u;
}

__device__ __forceinline__ uint32_t sptr(const void* p) {
    return (uint32_t)__cvta_generic_to_shared(p);
}

#define CP16(dst_s32, src_gen) \
    asm volatile("cp.async.cg.shared.global [%0], [%1], 16;" :: "r"(dst_s32), "l"(src_gen))
#define CP_COMMIT()  asm volatile("cp.async.commit_group;")
#define CP_WAIT0()   asm volatile("cp.async.wait_group 0;")
#define CP_WAIT1()   asm volatile("cp.async.wait_group 1;")
#define CP_WAIT2()   asm volatile("cp.async.wait_group 2;")

// ---------------------------------------------------------------------------
// Pre-round inputs to tf32 (RNA). One grid-stride pass over 5 segments.
// Feeding pre-rounded raw bits to mma == old inline cvt.rna path, bit-exact.
// ---------------------------------------------------------------------------
#define N4_X   (MTOT * HID / 4)          // 1048576
#define N4_WQ  (NH * FDIM * HID / 4)     // 65536
#define N4_WV  (HID * HID / 4)           // 262144
#define N4_TOT (N4_X + 2 * N4_WQ + 2 * N4_WV)

__global__ void round_inputs(const float* __restrict__ x,
                             const float* __restrict__ Wq, const float* __restrict__ Wk,
                             const float* __restrict__ Wv, const float* __restrict__ Wo,
                             float* __restrict__ xr, float* __restrict__ wqr,
                             float* __restrict__ wkr, float* __restrict__ wvr,
                             float* __restrict__ wor) {
    const int stride = gridDim.x * blockDim.x;
    for (int i = blockIdx.x * blockDim.x + threadIdx.x; i < N4_TOT; i += stride) {
        const float4* src;
        uint4* dst;
        int j = i;
        if (j < N4_X)                { src = (const float4*)x  + j; dst = (uint4*)xr  + j; }
        else if ((j -= N4_X) < N4_WQ)      { src = (const float4*)Wq + j; dst = (uint4*)wqr + j; }
        else if ((j -= N4_WQ) < N4_WQ)     { src = (const float4*)Wk + j; dst = (uint4*)wkr + j; }
        else if ((j -= N4_WQ) < N4_WV)     { src = (const float4*)Wv + j; dst = (uint4*)wvr + j; }
        else { j -= N4_WV;             src = (const float4*)Wo + j; dst = (uint4*)wor + j; }
        float4 f = *src;
        *dst = make_uint4(f2tf(f.x), f2tf(f.y), f2tf(f.z), f2tf(f.w));
    }
}

// ---------------------------------------------------------------------------
// tf32 GEMM tile v2: cp.async 3-stage pipeline, BK=8, inputs PRE-ROUNDED tf32
// (raw bits land directly in MMA layout — no cvt/LDG/STS in the mainloop).
// [128][12] rows (8 data + 4 pad): frag LDS pattern 12g+t hits 32 distinct
// banks; 16B chunks land at row*48B (+16) — aligned.
// FM=true: fused feature-map epilogue (layernorm -> *gamma+beta -> *scale).
// ---------------------------------------------------------------------------
template <bool FM>
__device__ __forceinline__ void gemm_cp_tile(uint32_t* __restrict__ smem,
                                             const float* __restrict__ A,
                                             const float* __restrict__ Bm,
                                             float* __restrict__ C,
                                             int m0g, int n0g, int K, int ldc,
                                             const float* __restrict__ gamma,
                                             const float* __restrict__ beta,
                                             float scale) {
    // A stage s at smem + s*1536 ([128][12]); B stage s at smem + 4608 + s*1536
    const int tid  = threadIdx.x;
    const int w    = tid >> 5;
    const int lane = tid & 31;
    const int g = lane >> 2;
    const int t = lane & 3;
    const int wm = (w >> 1) * 32;
    const int wn = (w & 1) * 64;

    const int crow = tid >> 1;           // 0..127
    const int cq   = (tid & 1) * 4;      // word offset 0 or 4 (16B chunk)

    const float* Agr = A  + (size_t)(m0g + crow) * K + cq;
    const float* Bgr = Bm + (size_t)(n0g + crow) * K + cq;
    const uint32_t sA = sptr(smem) + (crow * 12 + cq) * 4;
    const uint32_t sB = sA + 4608 * 4;

    auto issue = [&](int i, int bi) {
        CP16(sA + bi * 1536 * 4, Agr + i * 8);
        CP16(sB + bi * 1536 * 4, Bgr + i * 8);
        CP_COMMIT();
    };

    const int last = K / 8 - 1;          // 127
    issue(0, 0); issue(1, 1); issue(2, 2);

    float acc[2][8][4];
#pragma unroll
    for (int mi = 0; mi < 2; mi++)
#pragma unroll
        for (int ni = 0; ni < 8; ni++)
#pragma unroll
            for (int r = 0; r < 4; r++) acc[mi][ni][r] = 0.f;

    int buf = 0;
    for (int i = 0; i <= last; i++) {
        if (i + 2 <= last)      CP_WAIT2();
        else if (i + 1 <= last) CP_WAIT1();
        else                    CP_WAIT0();
        __syncthreads();   // tile i visible to all; buf (i+2)%3 (= tile i-1's) free

        if (i + 2 <= last) issue(i + 2, (i + 2) % 3);

        const uint32_t* As = smem + buf * 1536;
        const uint32_t* Bs = smem + 4608 + buf * 1536;

        uint32_t ar[2][4];
#pragma unroll
        for (int mi = 0; mi < 2; mi++) {
            ar[mi][0] = As[(wm + mi * 16 + g    ) * 12 + t];
            ar[mi][1] = As[(wm + mi * 16 + g + 8) * 12 + t];
            ar[mi][2] = As[(wm + mi * 16 + g    ) * 12 + t + 4];
            ar[mi][3] = As[(wm + mi * 16 + g + 8) * 12 + t + 4];
        }
        uint32_t br[8][2];
#pragma unroll
        for (int ni = 0; ni < 8; ni++) {
            br[ni][0] = Bs[(wn + ni * 8 + g) * 12 + t];
            br[ni][1] = Bs[(wn + ni * 8 + g) * 12 + t + 4];
        }
#pragma unroll
        for (int mi = 0; mi < 2; mi++)
#pragma unroll
            for (int ni = 0; ni < 8; ni++)
                mma_tf32(acc[mi][ni][0], acc[mi][ni][1], acc[mi][ni][2], acc[mi][ni][3],
                         ar[mi][0], ar[mi][1], ar[mi][2], ar[mi][3],
                         br[ni][0], br[ni][1]);

        buf = (buf + 1 == 3) ? 0 : buf + 1;
    }

    if (!FM) {
#pragma unroll
        for (int mi = 0; mi < 2; mi++) {
            const int row_lo = m0g + wm + mi * 16 + g;
#pragma unroll
            for (int ni = 0; ni < 8; ni++) {
                const int col = n0g + wn + ni * 8 + 2 * t;
                *(float2*)(C + (size_t)row_lo * ldc + col) =
                    make_float2(acc[mi][ni][0], acc[mi][ni][1]);
                *(float2*)(C + (size_t)(row_lo + 8) * ldc + col) =
                    make_float2(acc[mi][ni][2], acc[mi][ni][3]);
            }
        }
    } else {
        // Fused feature map: per 16-col head, one row's 16 values live in the
        // 4 lanes of this quad (4 each) — quad shfl reductions.
        const float g0 = __ldg(&gamma[2 * t]),     g1 = __ldg(&gamma[2 * t + 1]);
        const float g2 = __ldg(&gamma[8 + 2 * t]), g3 = __ldg(&gamma[8 + 2 * t + 1]);
        const float be0 = __ldg(&beta[2 * t]),     be1 = __ldg(&beta[2 * t + 1]);
        const float be2 = __ldg(&beta[8 + 2 * t]), be3 = __ldg(&beta[8 + 2 * t + 1]);
#pragma unroll
        for (int mi = 0; mi < 2; mi++) {
            const int row_lo = m0g + wm + mi * 16 + g;
#pragma unroll
            for (int j = 0; j < 4; j++) {
                float a0 = acc[mi][2*j][0], a1 = acc[mi][2*j][1];
                float a2 = acc[mi][2*j+1][0], a3 = acc[mi][2*j+1][1];
                float b0 = acc[mi][2*j][2], b1 = acc[mi][2*j][3];
                float b2 = acc[mi][2*j+1][2], b3 = acc[mi][2*j+1][3];
                float slo = (a0 + a1) + (a2 + a3);
                float shi = (b0 + b1) + (b2 + b3);
                slo += __shfl_xor_sync(0xffffffffu, slo, 1);
                slo += __shfl_xor_sync(0xffffffffu, slo, 2);
                shi += __shfl_xor_sync(0xffffffffu, shi, 1);
                shi += __shfl_xor_sync(0xffffffffu, shi, 2);
                const float mu_lo = slo * (1.f / 16.f);
                const float mu_hi = shi * (1.f / 16.f);
                a0 -= mu_lo; a1 -= mu_lo; a2 -= mu_lo; a3 -= mu_lo;
                b0 -= mu_hi; b1 -= mu_hi; b2 -= mu_hi; b3 -= mu_hi;
                float vlo = (a0*a0 + a1*a1) + (a2*a2 + a3*a3);
                float vhi = (b0*b0 + b1*b1) + (b2*b2 + b3*b3);
                vlo += __shfl_xor_sync(0xffffffffu, vlo, 1);
                vlo += __shfl_xor_sync(0xffffffffu, vlo, 2);
                vhi += __shfl_xor_sync(0xffffffffu, vhi, 1);
                vhi += __shfl_xor_sync(0xffffffffu, vhi, 2);
                const float r_lo = rsqrtf(vlo * (1.f / 16.f) + 1e-5f);
                const float r_hi = rsqrtf(vhi * (1.f / 16.f) + 1e-5f);
                const int col0 = n0g + wn + 16 * j + 2 * t;
                const int col1 = col0 + 8;
                float* rlo = C + (size_t)row_lo * ldc;
                float* rhi = C + (size_t)(row_lo + 8) * ldc;
                *(float2*)(rlo + col0) = make_float2((a0 * r_lo * g0 + be0) * scale,
                                                     (a1 * r_lo * g1 + be1) * scale);
                *(float2*)(rlo + col1) = make_float2((a2 * r_lo * g2 + be2) * scale,
                                                     (a3 * r_lo * g3 + be3) * scale);
                *(float2*)(rhi + col0) = make_float2((b0 * r_hi * g0 + be0) * scale,
                                                     (b1 * r_hi * g1 + be1) * scale);
                *(float2*)(rhi + col1) = make_float2((b2 * r_hi * g2 + be2) * scale,
                                                     (b3 * r_hi * g3 + be3) * scale);
            }
        }
    }
}

// Fused projection kernel: bx 0-1 -> Wq->q (+featmap, scale .25),
// bx 2-3 -> Wk->k (+featmap, scale 1), bx 4-11 -> Wv->v (plain).
__global__ void __launch_bounds__(256)
gemm_proj(const float* __restrict__ x,
          const float* __restrict__ Wq, const float* __restrict__ Wk,
          const float* __restrict__ Wv,
          float* __restrict__ q, float* __restrict__ k, float* __restrict__ v,
          const float* __restrict__ gamma, const float* __restrict__ beta) {
    __shared__ __align__(16) uint32_t smem[9216];   // 36 KB (3-stage A+B)
    const int bx = blockIdx.x;
    const int m0 = blockIdx.y * 128;
    if (bx < 2) {
        gemm_cp_tile<true>(smem, x, Wq, q, m0, bx * 128, HID, NH * FDIM,
                           gamma, beta, 0.25f);
    } else if (bx < 4) {
        gemm_cp_tile<true>(smem, x, Wk, k, m0, (bx - 2) * 128, HID, NH * FDIM,
                           gamma, beta, 1.0f);
    } else {
        gemm_cp_tile<false>(smem, x, Wv, v, m0, (bx - 4) * 128, HID, HID,
                            nullptr, nullptr, 1.0f);
    }
}

// O projection: plain tf32 GEMM (inputs pre-rounded)
__global__ void __launch_bounds__(256)
gemm_tf32_nt(const float* __restrict__ A, const float* __restrict__ Bm,
             float* __restrict__ C, int K, int N) {
    __shared__ __align__(16) uint32_t smem[9216];   // 36 KB
    gemm_cp_tile<false>(smem, A, Bm, C, blockIdx.y * 128, blockIdx.x * 128,
                        K, N, nullptr, nullptr, 1.0f);
}

// ---------------------------------------------------------------------------
// Tensor-core causal quadratic attention v4 (R10, measured 141-147 us);
// epilogue now stores o tf32-RNA-rounded (bit-exact with the old O-GEMM
// inline cvt path).
// ---------------------------------------------------------------------------
__global__ void __launch_bounds__(256)
attn_mma(const float* __restrict__ q, const float* __restrict__ k,
         const float* __restrict__ v, float* __restrict__ o_) {
    __shared__ __align__(16) uint32_t pool[11008];   // 43 KB
    uint32_t* const raw_k = pool;          // [64][16] raw fp32 bits
    uint32_t* const raw_v = pool + 1024;   // [64][64] raw fp32 bits
    uint32_t* const qs    = pool;          // [128][20] (aliases staging; once)
    uint32_t* const ks    = pool + 5120;   // [64][20] tf32
    uint32_t* const vs    = pool + 6400;   // [64][72] tf32

    const int bh = blockIdx.y;
    const int b = bh >> 4;
    const int h = bh & 15;
    const int qt = gridDim.x - 1 - blockIdx.x;   // heavy blocks first (128-row tile)
    const int tid = threadIdx.x;
    const int lane = tid & 31;
    const int w = tid >> 5;
    const int wl = w & 3;                  // warp index within group
    const int isB = w >> 2;                // 0: q rows [0,64), 1: [64,128)
    const int goff = isB * 64;
    const int g = lane >> 2;
    const int t = lane & 3;

    // ---- fill qs (once): 128 rows x 16 fd, tf32; then extract frags, release
    {
        const int row = tid >> 1, c0 = (tid & 1) * 8;
        const float* src = q + (size_t)(b * LL + qt * 128 + row) * (NH * FDIM) + h * FDIM + c0;
        float4 f0 = ((const float4*)src)[0];
        float4 f1 = ((const float4*)src)[1];
        *(uint4*)(qs + row * 20 + c0) =
            make_uint4(f2tf(f0.x), f2tf(f0.y), f2tf(f0.z), f2tf(f0.w));
        *(uint4*)(qs + row * 20 + c0 + 4) =
            make_uint4(f2tf(f1.x), f2tf(f1.y), f2tf(f1.z), f2tf(f1.w));
    }
    __syncthreads();

    uint32_t qa[2][4];
#pragma unroll
    for (int kc = 0; kc < 2; kc++) {
        const int r0 = goff + wl * 16;
        qa[kc][0] = qs[(r0 + g    ) * 20 + kc * 8 + t];
        qa[kc][1] = qs[(r0 + g + 8) * 20 + kc * 8 + t];
        qa[kc][2] = qs[(r0 + g    ) * 20 + kc * 8 + t + 4];
        qa[kc][3] = qs[(r0 + g + 8) * 20 + kc * 8 + t + 4];
    }
    __syncthreads();   // all reads of qs done -> staging region free

    const float* kbase = k + (size_t)(b * LL) * (NH * FDIM) + h * FDIM;  // row stride 256
    const float* vbase = v + (size_t)(b * LL) * HID + h * HDIM;          // row stride 1024

    // cp.async one 64-key tile (k: 256 16B-chunks, v: 1024 16B-chunks; 256 thr)
    auto issue_tile = [&](int kt) {
        const float* kb = kbase + (size_t)(kt * 64) * (NH * FDIM);
        const float* vb = vbase + (size_t)(kt * 64) * HID;
        {
            const int row = tid >> 2, quad = tid & 3;
            CP16(sptr(raw_k + row * 16 + quad * 4), kb + row * 256 + quad * 4);
        }
#pragma unroll
        for (int i = 0; i < 4; i++) {
            const int c = tid + 256 * i;
            const int row = c >> 4, quad = c & 15;
            CP16(sptr(raw_v + row * 64 + quad * 4), vb + row * 1024 + quad * 4);
        }
        CP_COMMIT();
    };

    issue_tile(0);

    float oc[8][4];
#pragma unroll
    for (int nt = 0; nt < 8; nt++)
#pragma unroll
        for (int r = 0; r < 4; r++) oc[nt][r] = 0.f;
    float z_lo = 0.f, z_hi = 0.f;

    const int src1 = (lane & ~3) | (t >> 1);
    const int src2 = src1 | 2;

    const int last_kt = 2 * qt + 1;
    const int my_diag = 2 * qt + isB;      // this group's diagonal key tile

    for (int kt = 0; kt <= last_kt; kt++) {
        CP_WAIT0();
        __syncthreads();   // staging(kt) visible; ks/vs free (prev MMAs done)

        // ---- convert raw fp32 -> tf32 padded tiles (256 threads)
        {
            const int row = tid >> 2, quad = tid & 3;
            float4 f = *(const float4*)(raw_k + row * 16 + quad * 4);
            *(uint4*)(ks + row * 20 + quad * 4) =
                make_uint4(f2tf(f.x), f2tf(f.y), f2tf(f.z), f2tf(f.w));
        }
#pragma unroll
        for (int i = 0; i < 4; i++) {
            const int c = tid + 256 * i;
            const int row = c >> 4, quad = c & 15;
            float4 f = *(const float4*)(raw_v + row * 64 + quad * 4);
            *(uint4*)(vs + row * 72 + quad * 4) =
                make_uint4(f2tf(f.x), f2tf(f.y), f2tf(f.z), f2tf(f.w));
        }
        __syncthreads();   // convert done: staging free, tf32 tiles ready

        if (kt < last_kt) issue_tile(kt + 1);   // overlaps with MMA stages

        if (kt > my_diag) continue;   // group A idles on the final tile

        // ---- stage 1: S = Q K^T
        float sc[8][4];
#pragma unroll
        for (int nt = 0; nt < 8; nt++) {
            sc[nt][0] = sc[nt][1] = sc[nt][2] = sc[nt][3] = 0.f;
#pragma unroll
            for (int kc = 0; kc < 2; kc++) {
                uint32_t b0 = ks[(nt * 8 + g) * 20 + kc * 8 + t];
                uint32_t b1 = ks[(nt * 8 + g) * 20 + kc * 8 + t + 4];
                mma_tf32(sc[nt][0], sc[nt][1], sc[nt][2], sc[nt][3],
                         qa[kc][0], qa[kc][1], qa[kc][2], qa[kc][3], b0, b1);
            }
        }

        // ---- stage 2: causal mask (diag tile), square, z accum, cvt to tf32
        const bool diag = (kt == my_diag);
        const int rlo = wl * 16 + g;      // row within this group's 64 rows
        const int rhi = rlo + 8;
        uint32_t scq[8][4];
#pragma unroll
        for (int nt = 0; nt < 8; nt++) {
            const int c0col = nt * 8 + 2 * t;
            float s0 = sc[nt][0], s1 = sc[nt][1], s2 = sc[nt][2], s3 = sc[nt][3];
            if (diag) {
                if (c0col     > rlo) s0 = 0.f;
                if (c0col + 1 > rlo) s1 = 0.f;
                if (c0col     > rhi) s2 = 0.f;
                if (c0col + 1 > rhi) s3 = 0.f;
            }
            s0 *= s0; s1 *= s1; s2 *= s2; s3 *= s3;
            z_lo += s0 + s1;
            z_hi += s2 + s3;
            scq[nt][0] = f2tf(s0); scq[nt][1] = f2tf(s1);
            scq[nt][2] = f2tf(s2); scq[nt][3] = f2tf(s3);
        }

        // ---- stage 3: O += S V, S relayout via shuffles (C-frag -> A-frag)
#pragma unroll
        for (int kc = 0; kc < 8; kc++) {
            uint32_t u0 = __shfl_sync(0xffffffffu, scq[kc][0], src1);
            uint32_t u1 = __shfl_sync(0xffffffffu, scq[kc][1], src1);
            uint32_t u2 = __shfl_sync(0xffffffffu, scq[kc][2], src1);
            uint32_t u3 = __shfl_sync(0xffffffffu, scq[kc][3], src1);
            uint32_t w0 = __shfl_sync(0xffffffffu, scq[kc][0], src2);
            uint32_t w1 = __shfl_sync(0xffffffffu, scq[kc][1], src2);
            uint32_t w2 = __shfl_sync(0xffffffffu, scq[kc][2], src2);
            uint32_t w3 = __shfl_sync(0xffffffffu, scq[kc][3], src2);
            const bool odd = (t & 1);
            const uint32_t sa0 = odd ? u1 : u0;
            const uint32_t sa1 = odd ? u3 : u2;
            const uint32_t sa2 = odd ? w1 : w0;
            const uint32_t sa3 = odd ? w3 : w2;
#pragma unroll
            for (int nt = 0; nt < 8; nt++) {
                uint32_t vb0 = vs[(kc * 8 + t    ) * 72 + nt * 8 + g];
                uint32_t vb1 = vs[(kc * 8 + t + 4) * 72 + nt * 8 + g];
                mma_tf32(oc[nt][0], oc[nt][1], oc[nt][2], oc[nt][3],
                         sa0, sa1, sa2, sa3, vb0, vb1);
            }
        }
    }

    // ---- epilogue: z reduce, normalize, store o TF32-ROUNDED (feeds O-GEMM)
    z_lo += __shfl_xor_sync(0xffffffffu, z_lo, 1);
    z_lo += __shfl_xor_sync(0xffffffffu, z_lo, 2);
    z_hi += __shfl_xor_sync(0xffffffffu, z_hi, 1);
    z_hi += __shfl_xor_sync(0xffffffffu, z_hi, 2);
    const float inv_lo = 1.f / (z_lo + 1e-5f);
    const float inv_hi = 1.f / (z_hi + 1e-5f);

    const int qrow_lo = qt * 128 + goff + wl * 16 + g;
    float* obase = o_ + (size_t)(b * LL) * HID + h * HDIM;
#pragma unroll
    for (int nt = 0; nt < 8; nt++) {
        const int col = nt * 8 + 2 * t;
        *(uint2*)(obase + (size_t)qrow_lo * HID + col) =
            make_uint2(f2tf(oc[nt][0] * inv_lo), f2tf(oc[nt][1] * inv_lo));
        *(uint2*)(obase + (size_t)(qrow_lo + 8) * HID + col) =
            make_uint2(f2tf(oc[nt][2] * inv_hi), f2tf(oc[nt][3] * inv_hi));
    }
}

// ---------------------------------------------------------------------------
extern "C" void kernel_launch(void* const* d_in, const int* in_sizes, int n_in,
                              void* d_out, int out_size) {
    const float* x     = (const float*)d_in[0];   // (2,2048,1024)
    const float* Wq    = (const float*)d_in[1];   // (256,1024)
    const float* Wk    = (const float*)d_in[2];   // (256,1024)
    const float* Wv    = (const float*)d_in[3];   // (1024,1024)
    const float* Wo    = (const float*)d_in[4];   // (1024,1024)
    const float* gamma = (const float*)d_in[5];   // (16,)
    const float* beta  = (const float*)d_in[6];   // (16,)
    float* out = (float*)d_out;

    float *q, *k, *v, *o, *xr, *wqr, *wkr, *wvr, *wor;
    cudaGetSymbolAddress((void**)&q, g_q);
    cudaGetSymbolAddress((void**)&k, g_k);
    cudaGetSymbolAddress((void**)&v, g_v);
    cudaGetSymbolAddress((void**)&o, g_o);
    cudaGetSymbolAddress((void**)&xr, g_xr);
    cudaGetSymbolAddress((void**)&wqr, g_wqr);
    cudaGetSymbolAddress((void**)&wkr, g_wkr);
    cudaGetSymbolAddress((void**)&wvr, g_wvr);
    cudaGetSymbolAddress((void**)&wor, g_wor);

    // Pre-round GEMM inputs to tf32 (enables raw cp.async into MMA tiles)
    round_inputs<<<592, 256>>>(x, Wq, Wk, Wv, Wo, xr, wqr, wkr, wvr, wor);

    // Fused Q+K(+featmap) and V projections (384 uniform CTAs, cp.async GEMM)
    gemm_proj<<<dim3(12, 32), 256>>>(xr, wqr, wkr, wvr, q, k, v, gamma, beta);

    // Tensor-core causal quadratic attention (R10 v4; epilogue rounds o)
    attn_mma<<<dim3(LL / 128, BB * NH), 256>>>(q, k, v, o);

    // Output projection (cp.async GEMM, pre-rounded inputs)
    gemm_tf32_nt<<<dim3(HID / 128, MTOT / 128), 256>>>(o, wor, out, HID, HID);
}

// round 17
// speedup vs baseline: 1.2347x; 1.0576x over previous
#include <cuda_runtime.h>
#include <cstdint>

#define BB 2
#define LL 2048
#define HID 1024
#define NH 16
#define FDIM 16
#define HDIM 64
#define MTOT (BB*LL)   // 4096

// Scratch (static __device__ — no allocation allowed)
__device__ float g_q[MTOT * NH * FDIM];   // 4 MB
__device__ float g_k[MTOT * NH * FDIM];   // 4 MB
__device__ float g_v[MTOT * HID];         // 16 MB
__device__ float g_o[MTOT * HID];         // 16 MB (tf32-rounded by attn epilogue)
// tf32-rounded copies of GEMM inputs (lets cp.async feed MMA tiles raw)
__device__ float g_xr[MTOT * HID];        // 16 MB
__device__ float g_wqr[NH * FDIM * HID];  // 1 MB
__device__ float g_wkr[NH * FDIM * HID];  // 1 MB
__device__ float g_wvr[HID * HID];        // 4 MB
__device__ float g_wor[HID * HID];        // 4 MB

// ---------------------------------------------------------------------------
// tf32 helpers (fragment layouts validated in R6/R7)
// ---------------------------------------------------------------------------
__device__ __forceinline__ void mma_tf32(float& d0, float& d1, float& d2, float& d3,
                                         uint32_t a0, uint32_t a1, uint32_t a2, uint32_t a3,
                                         uint32_t b0, uint32_t b1) {
    asm volatile("mma.sync.aligned.m16n8k8.row.col.f32.tf32.tf32.f32 "
                 "{%0,%1,%2,%3}, {%4,%5,%6,%7}, {%8,%9}, {%0,%1,%2,%3};"
                 : "+f"(d0), "+f"(d1), "+f"(d2), "+f"(d3)
                 : "r"(a0), "r"(a1), "r"(a2), "r"(a3), "r"(b0), "r"(b1));
}

__device__ __forceinline__ uint32_t f2tf(float f) {
    uint32_t u;
    asm("cvt.rna.tf32.f32 %0, %1;" : "=r"(u) : "f"(f));
    return u;
}

__device__ __forceinline__ uint32_t sptr(const void* p) {
    return (uint32_t)__cvta_generic_to_shared(p);
}

#define CP16(dst_s32, src_gen) \
    asm volatile("cp.async.cg.shared.global [%0], [%1], 16;" :: "r"(dst_s32), "l"(src_gen))
#define CP_COMMIT()  asm volatile("cp.async.commit_group;")
#define CP_WAIT0()   asm volatile("cp.async.wait_group 0;")
#define CP_WAIT1()   asm volatile("cp.async.wait_group 1;")
#define CP_WAIT2()   asm volatile("cp.async.wait_group 2;")

// ---------------------------------------------------------------------------
// Pre-round inputs to tf32 (RNA). One grid-stride pass over 5 segments.
// Feeding pre-rounded raw bits to mma == old inline cvt.rna path, bit-exact.
// ---------------------------------------------------------------------------
#define N4_X   (MTOT * HID / 4)          // 1048576
#define N4_WQ  (NH * FDIM * HID / 4)     // 65536
#define N4_WV  (HID * HID / 4)           // 262144
#define N4_TOT (N4_X + 2 * N4_WQ + 2 * N4_WV)

__global__ void round_inputs(const float* __restrict__ x,
                             const float* __restrict__ Wq, const float* __restrict__ Wk,
                             const float* __restrict__ Wv, const float* __restrict__ Wo,
                             float* __restrict__ xr, float* __restrict__ wqr,
                             float* __restrict__ wkr, float* __restrict__ wvr,
                             float* __restrict__ wor) {
    const int stride = gridDim.x * blockDim.x;
    for (int i = blockIdx.x * blockDim.x + threadIdx.x; i < N4_TOT; i += stride) {
        const float4* src;
        uint4* dst;
        int j = i;
        if (j < N4_X)                { src = (const float4*)x  + j; dst = (uint4*)xr  + j; }
        else if ((j -= N4_X) < N4_WQ)      { src = (const float4*)Wq + j; dst = (uint4*)wqr + j; }
        else if ((j -= N4_WQ) < N4_WQ)     { src = (const float4*)Wk + j; dst = (uint4*)wkr + j; }
        else if ((j -= N4_WQ) < N4_WV)     { src = (const float4*)Wv + j; dst = (uint4*)wvr + j; }
        else { j -= N4_WV;             src = (const float4*)Wo + j; dst = (uint4*)wor + j; }
        float4 f = *src;
        *dst = make_uint4(f2tf(f.x), f2tf(f.y), f2tf(f.z), f2tf(f.w));
    }
}

// ---------------------------------------------------------------------------
// tf32 GEMM tile v3: BK=16, 3-stage cp.async pipeline, inputs PRE-ROUNDED
// tf32 (raw bits land directly in the proven stride-20 MMA layout; chunks at
// word offsets {0,4,8,12} of each 80-byte row — 16B-aligned).
// 32 MMAs/warp per barrier (2x R16), 64 barriers (0.5x), 2-tile lookahead.
// Dynamic smem: 3 stages x (A 10KB + B 10KB) = 60 KB.
// FM=true: fused feature-map epilogue (layernorm -> *gamma+beta -> *scale).
// ---------------------------------------------------------------------------
template <bool FM>
__device__ __forceinline__ void gemm_cp_tile(uint32_t* __restrict__ smem,
                                             const float* __restrict__ A,
                                             const float* __restrict__ Bm,
                                             float* __restrict__ C,
                                             int m0g, int n0g, int K, int ldc,
                                             const float* __restrict__ gamma,
                                             const float* __restrict__ beta,
                                             float scale) {
    // A stage s at smem + s*2560 ([128][20]); B stage s at smem + 7680 + s*2560
    const int tid  = threadIdx.x;
    const int w    = tid >> 5;
    const int lane = tid & 31;
    const int g = lane >> 2;
    const int t = lane & 3;
    const int wm = (w >> 1) * 32;
    const int wn = (w & 1) * 64;

    const int crow = tid >> 1;           // 0..127
    const int c8   = (tid & 1) * 8;      // word offset 0 or 8 (two 16B chunks)

    const float* Agr = A  + (size_t)(m0g + crow) * K + c8;
    const float* Bgr = Bm + (size_t)(n0g + crow) * K + c8;
    const uint32_t sA = sptr(smem) + (crow * 20 + c8) * 4;
    const uint32_t sB = sA + 7680 * 4;

    auto issue = [&](int i, int bi) {
        const uint32_t da = sA + bi * 2560 * 4;
        const uint32_t db = sB + bi * 2560 * 4;
        CP16(da,      Agr + i * 16);
        CP16(da + 16, Agr + i * 16 + 4);
        CP16(db,      Bgr + i * 16);
        CP16(db + 16, Bgr + i * 16 + 4);
        CP_COMMIT();
    };

    const int last = K / 16 - 1;         // 63
    issue(0, 0); issue(1, 1); issue(2, 2);

    float acc[2][8][4];
#pragma unroll
    for (int mi = 0; mi < 2; mi++)
#pragma unroll
        for (int ni = 0; ni < 8; ni++)
#pragma unroll
            for (int r = 0; r < 4; r++) acc[mi][ni][r] = 0.f;

    int buf = 0;
    for (int i = 0; i <= last; i++) {
        if (i + 2 <= last)      CP_WAIT2();
        else if (i + 1 <= last) CP_WAIT1();
        else                    CP_WAIT0();
        __syncthreads();   // tile i visible; buf (i+2)%3 (= tile i-1's) free

        if (i + 2 <= last) issue(i + 2, (i + 2) % 3);

        const uint32_t* As = smem + buf * 2560;
        const uint32_t* Bs = smem + 7680 + buf * 2560;

#pragma unroll
        for (int kc = 0; kc < 2; kc++) {
            uint32_t ar[2][4];
#pragma unroll
            for (int mi = 0; mi < 2; mi++) {
                ar[mi][0] = As[(wm + mi * 16 + g    ) * 20 + kc * 8 + t];
                ar[mi][1] = As[(wm + mi * 16 + g + 8) * 20 + kc * 8 + t];
                ar[mi][2] = As[(wm + mi * 16 + g    ) * 20 + kc * 8 + t + 4];
                ar[mi][3] = As[(wm + mi * 16 + g + 8) * 20 + kc * 8 + t + 4];
            }
            uint32_t br[8][2];
#pragma unroll
            for (int ni = 0; ni < 8; ni++) {
                br[ni][0] = Bs[(wn + ni * 8 + g) * 20 + kc * 8 + t];
                br[ni][1] = Bs[(wn + ni * 8 + g) * 20 + kc * 8 + t + 4];
            }
#pragma unroll
            for (int mi = 0; mi < 2; mi++)
#pragma unroll
                for (int ni = 0; ni < 8; ni++)
                    mma_tf32(acc[mi][ni][0], acc[mi][ni][1], acc[mi][ni][2], acc[mi][ni][3],
                             ar[mi][0], ar[mi][1], ar[mi][2], ar[mi][3],
                             br[ni][0], br[ni][1]);
        }

        buf = (buf + 1 == 3) ? 0 : buf + 1;
    }

    if (!FM) {
#pragma unroll
        for (int mi = 0; mi < 2; mi++) {
            const int row_lo = m0g + wm + mi * 16 + g;
#pragma unroll
            for (int ni = 0; ni < 8; ni++) {
                const int col = n0g + wn + ni * 8 + 2 * t;
                *(float2*)(C + (size_t)row_lo * ldc + col) =
                    make_float2(acc[mi][ni][0], acc[mi][ni][1]);
                *(float2*)(C + (size_t)(row_lo + 8) * ldc + col) =
                    make_float2(acc[mi][ni][2], acc[mi][ni][3]);
            }
        }
    } else {
        // Fused feature map: per 16-col head, one row's 16 values live in the
        // 4 lanes of this quad (4 each) — quad shfl reductions.
        const float g0 = __ldg(&gamma[2 * t]),     g1 = __ldg(&gamma[2 * t + 1]);
        const float g2 = __ldg(&gamma[8 + 2 * t]), g3 = __ldg(&gamma[8 + 2 * t + 1]);
        const float be0 = __ldg(&beta[2 * t]),     be1 = __ldg(&beta[2 * t + 1]);
        const float be2 = __ldg(&beta[8 + 2 * t]), be3 = __ldg(&beta[8 + 2 * t + 1]);
#pragma unroll
        for (int mi = 0; mi < 2; mi++) {
            const int row_lo = m0g + wm + mi * 16 + g;
#pragma unroll
            for (int j = 0; j < 4; j++) {
                float a0 = acc[mi][2*j][0], a1 = acc[mi][2*j][1];
                float a2 = acc[mi][2*j+1][0], a3 = acc[mi][2*j+1][1];
                float b0 = acc[mi][2*j][2], b1 = acc[mi][2*j][3];
                float b2 = acc[mi][2*j+1][2], b3 = acc[mi][2*j+1][3];
                float slo = (a0 + a1) + (a2 + a3);
                float shi = (b0 + b1) + (b2 + b3);
                slo += __shfl_xor_sync(0xffffffffu, slo, 1);
                slo += __shfl_xor_sync(0xffffffffu, slo, 2);
                shi += __shfl_xor_sync(0xffffffffu, shi, 1);
                shi += __shfl_xor_sync(0xffffffffu, shi, 2);
                const float mu_lo = slo * (1.f / 16.f);
                const float mu_hi = shi * (1.f / 16.f);
                a0 -= mu_lo; a1 -= mu_lo; a2 -= mu_lo; a3 -= mu_lo;
                b0 -= mu_hi; b1 -= mu_hi; b2 -= mu_hi; b3 -= mu_hi;
                float vlo = (a0*a0 + a1*a1) + (a2*a2 + a3*a3);
                float vhi = (b0*b0 + b1*b1) + (b2*b2 + b3*b3);
                vlo += __shfl_xor_sync(0xffffffffu, vlo, 1);
                vlo += __shfl_xor_sync(0xffffffffu, vlo, 2);
                vhi += __shfl_xor_sync(0xffffffffu, vhi, 1);
                vhi += __shfl_xor_sync(0xffffffffu, vhi, 2);
                const float r_lo = rsqrtf(vlo * (1.f / 16.f) + 1e-5f);
                const float r_hi = rsqrtf(vhi * (1.f / 16.f) + 1e-5f);
                const int col0 = n0g + wn + 16 * j + 2 * t;
                const int col1 = col0 + 8;
                float* rlo = C + (size_t)row_lo * ldc;
                float* rhi = C + (size_t)(row_lo + 8) * ldc;
                *(float2*)(rlo + col0) = make_float2((a0 * r_lo * g0 + be0) * scale,
                                                     (a1 * r_lo * g1 + be1) * scale);
                *(float2*)(rlo + col1) = make_float2((a2 * r_lo * g2 + be2) * scale,
                                                     (a3 * r_lo * g3 + be3) * scale);
                *(float2*)(rhi + col0) = make_float2((b0 * r_hi * g0 + be0) * scale,
                                                     (b1 * r_hi * g1 + be1) * scale);
                *(float2*)(rhi + col1) = make_float2((b2 * r_hi * g2 + be2) * scale,
                                                     (b3 * r_hi * g3 + be3) * scale);
            }
        }
    }
}

// Fused projection kernel: bx 0-1 -> Wq->q (+featmap, scale .25),
// bx 2-3 -> Wk->k (+featmap, scale 1), bx 4-11 -> Wv->v (plain).
__global__ void __launch_bounds__(256)
gemm_proj(const float* __restrict__ x,
          const float* __restrict__ Wq, const float* __restrict__ Wk,
          const float* __restrict__ Wv,
          float* __restrict__ q, float* __restrict__ k, float* __restrict__ v,
          const float* __restrict__ gamma, const float* __restrict__ beta) {
    extern __shared__ __align__(16) uint32_t smem[];   // 60 KB dynamic
    const int bx = blockIdx.x;
    const int m0 = blockIdx.y * 128;
    if (bx < 2) {
        gemm_cp_tile<true>(smem, x, Wq, q, m0, bx * 128, HID, NH * FDIM,
                           gamma, beta, 0.25f);
    } else if (bx < 4) {
        gemm_cp_tile<true>(smem, x, Wk, k, m0, (bx - 2) * 128, HID, NH * FDIM,
                           gamma, beta, 1.0f);
    } else {
        gemm_cp_tile<false>(smem, x, Wv, v, m0, (bx - 4) * 128, HID, HID,
                            nullptr, nullptr, 1.0f);
    }
}

// O projection: plain tf32 GEMM (inputs pre-rounded)
__global__ void __launch_bounds__(256)
gemm_tf32_nt(const float* __restrict__ A, const float* __restrict__ Bm,
             float* __restrict__ C, int K, int N) {
    extern __shared__ __align__(16) uint32_t smem[];   // 60 KB dynamic
    gemm_cp_tile<false>(smem, A, Bm, C, blockIdx.y * 128, blockIdx.x * 128,
                        K, N, nullptr, nullptr, 1.0f);
}

// ---------------------------------------------------------------------------
// Tensor-core causal quadratic attention v4 (R10, measured 141-147 us);
// epilogue stores o tf32-RNA-rounded (feeds O-GEMM raw path, bit-exact).
// ---------------------------------------------------------------------------
__global__ void __launch_bounds__(256)
attn_mma(const float* __restrict__ q, const float* __restrict__ k,
         const float* __restrict__ v, float* __restrict__ o_) {
    __shared__ __align__(16) uint32_t pool[11008];   // 43 KB
    uint32_t* const raw_k = pool;          // [64][16] raw fp32 bits
    uint32_t* const raw_v = pool + 1024;   // [64][64] raw fp32 bits
    uint32_t* const qs    = pool;          // [128][20] (aliases staging; once)
    uint32_t* const ks    = pool + 5120;   // [64][20] tf32
    uint32_t* const vs    = pool + 6400;   // [64][72] tf32

    const int bh = blockIdx.y;
    const int b = bh >> 4;
    const int h = bh & 15;
    const int qt = gridDim.x - 1 - blockIdx.x;   // heavy blocks first (128-row tile)
    const int tid = threadIdx.x;
    const int lane = tid & 31;
    const int w = tid >> 5;
    const int wl = w & 3;                  // warp index within group
    const int isB = w >> 2;                // 0: q rows [0,64), 1: [64,128)
    const int goff = isB * 64;
    const int g = lane >> 2;
    const int t = lane & 3;

    // ---- fill qs (once): 128 rows x 16 fd, tf32; then extract frags, release
    {
        const int row = tid >> 1, c0 = (tid & 1) * 8;
        const float* src = q + (size_t)(b * LL + qt * 128 + row) * (NH * FDIM) + h * FDIM + c0;
        float4 f0 = ((const float4*)src)[0];
        float4 f1 = ((const float4*)src)[1];
        *(uint4*)(qs + row * 20 + c0) =
            make_uint4(f2tf(f0.x), f2tf(f0.y), f2tf(f0.z), f2tf(f0.w));
        *(uint4*)(qs + row * 20 + c0 + 4) =
            make_uint4(f2tf(f1.x), f2tf(f1.y), f2tf(f1.z), f2tf(f1.w));
    }
    __syncthreads();

    uint32_t qa[2][4];
#pragma unroll
    for (int kc = 0; kc < 2; kc++) {
        const int r0 = goff + wl * 16;
        qa[kc][0] = qs[(r0 + g    ) * 20 + kc * 8 + t];
        qa[kc][1] = qs[(r0 + g + 8) * 20 + kc * 8 + t];
        qa[kc][2] = qs[(r0 + g    ) * 20 + kc * 8 + t + 4];
        qa[kc][3] = qs[(r0 + g + 8) * 20 + kc * 8 + t + 4];
    }
    __syncthreads();   // all reads of qs done -> staging region free

    const float* kbase = k + (size_t)(b * LL) * (NH * FDIM) + h * FDIM;  // row stride 256
    const float* vbase = v + (size_t)(b * LL) * HID + h * HDIM;          // row stride 1024

    // cp.async one 64-key tile (k: 256 16B-chunks, v: 1024 16B-chunks; 256 thr)
    auto issue_tile = [&](int kt) {
        const float* kb = kbase + (size_t)(kt * 64) * (NH * FDIM);
        const float* vb = vbase + (size_t)(kt * 64) * HID;
        {
            const int row = tid >> 2, quad = tid & 3;
            CP16(sptr(raw_k + row * 16 + quad * 4), kb + row * 256 + quad * 4);
        }
#pragma unroll
        for (int i = 0; i < 4; i++) {
            const int c = tid + 256 * i;
            const int row = c >> 4, quad = c & 15;
            CP16(sptr(raw_v + row * 64 + quad * 4), vb + row * 1024 + quad * 4);
        }
        CP_COMMIT();
    };

    issue_tile(0);

    float oc[8][4];
#pragma unroll
    for (int nt = 0; nt < 8; nt++)
#pragma unroll
        for (int r = 0; r < 4; r++) oc[nt][r] = 0.f;
    float z_lo = 0.f, z_hi = 0.f;

    const int src1 = (lane & ~3) | (t >> 1);
    const int src2 = src1 | 2;

    const int last_kt = 2 * qt + 1;
    const int my_diag = 2 * qt + isB;      // this group's diagonal key tile

    for (int kt = 0; kt <= last_kt; kt++) {
        CP_WAIT0();
        __syncthreads();   // staging(kt) visible; ks/vs free (prev MMAs done)

        // ---- convert raw fp32 -> tf32 padded tiles (256 threads)
        {
            const int row = tid >> 2, quad = tid & 3;
            float4 f = *(const float4*)(raw_k + row * 16 + quad * 4);
            *(uint4*)(ks + row * 20 + quad * 4) =
                make_uint4(f2tf(f.x), f2tf(f.y), f2tf(f.z), f2tf(f.w));
        }
#pragma unroll
        for (int i = 0; i < 4; i++) {
            const int c = tid + 256 * i;
            const int row = c >> 4, quad = c & 15;
            float4 f = *(const float4*)(raw_v + row * 64 + quad * 4);
            *(uint4*)(vs + row * 72 + quad * 4) =
                make_uint4(f2tf(f.x), f2tf(f.y), f2tf(f.z), f2tf(f.w));
        }
        __syncthreads();   // convert done: staging free, tf32 tiles ready

        if (kt < last_kt) issue_tile(kt + 1);   // overlaps with MMA stages

        if (kt > my_diag) continue;   // group A idles on the final tile

        // ---- stage 1: S = Q K^T
        float sc[8][4];
#pragma unroll
        for (int nt = 0; nt < 8; nt++) {
            sc[nt][0] = sc[nt][1] = sc[nt][2] = sc[nt][3] = 0.f;
#pragma unroll
            for (int kc = 0; kc < 2; kc++) {
                uint32_t b0 = ks[(nt * 8 + g) * 20 + kc * 8 + t];
                uint32_t b1 = ks[(nt * 8 + g) * 20 + kc * 8 + t + 4];
                mma_tf32(sc[nt][0], sc[nt][1], sc[nt][2], sc[nt][3],
                         qa[kc][0], qa[kc][1], qa[kc][2], qa[kc][3], b0, b1);
            }
        }

        // ---- stage 2: causal mask (diag tile), square, z accum, cvt to tf32
        const bool diag = (kt == my_diag);
        const int rlo = wl * 16 + g;      // row within this group's 64 rows
        const int rhi = rlo + 8;
        uint32_t scq[8][4];
#pragma unroll
        for (int nt = 0; nt < 8; nt++) {
            const int c0col = nt * 8 + 2 * t;
            float s0 = sc[nt][0], s1 = sc[nt][1], s2 = sc[nt][2], s3 = sc[nt][3];
            if (diag) {
                if (c0col     > rlo) s0 = 0.f;
                if (c0col + 1 > rlo) s1 = 0.f;
                if (c0col     > rhi) s2 = 0.f;
                if (c0col + 1 > rhi) s3 = 0.f;
            }
            s0 *= s0; s1 *= s1; s2 *= s2; s3 *= s3;
            z_lo += s0 + s1;
            z_hi += s2 + s3;
            scq[nt][0] = f2tf(s0); scq[nt][1] = f2tf(s1);
            scq[nt][2] = f2tf(s2); scq[nt][3] = f2tf(s3);
        }

        // ---- stage 3: O += S V, S relayout via shuffles (C-frag -> A-frag)
#pragma unroll
        for (int kc = 0; kc < 8; kc++) {
            uint32_t u0 = __shfl_sync(0xffffffffu, scq[kc][0], src1);
            uint32_t u1 = __shfl_sync(0xffffffffu, scq[kc][1], src1);
            uint32_t u2 = __shfl_sync(0xffffffffu, scq[kc][2], src1);
            uint32_t u3 = __shfl_sync(0xffffffffu, scq[kc][3], src1);
            uint32_t w0 = __shfl_sync(0xffffffffu, scq[kc][0], src2);
            uint32_t w1 = __shfl_sync(0xffffffffu, scq[kc][1], src2);
            uint32_t w2 = __shfl_sync(0xffffffffu, scq[kc][2], src2);
            uint32_t w3 = __shfl_sync(0xffffffffu, scq[kc][3], src2);
            const bool odd = (t & 1);
            const uint32_t sa0 = odd ? u1 : u0;
            const uint32_t sa1 = odd ? u3 : u2;
            const uint32_t sa2 = odd ? w1 : w0;
            const uint32_t sa3 = odd ? w3 : w2;
#pragma unroll
            for (int nt = 0; nt < 8; nt++) {
                uint32_t vb0 = vs[(kc * 8 + t    ) * 72 + nt * 8 + g];
                uint32_t vb1 = vs[(kc * 8 + t + 4) * 72 + nt * 8 + g];
                mma_tf32(oc[nt][0], oc[nt][1], oc[nt][2], oc[nt][3],
                         sa0, sa1, sa2, sa3, vb0, vb1);
            }
        }
    }

    // ---- epilogue: z reduce, normalize, store o TF32-ROUNDED (feeds O-GEMM)
    z_lo += __shfl_xor_sync(0xffffffffu, z_lo, 1);
    z_lo += __shfl_xor_sync(0xffffffffu, z_lo, 2);
    z_hi += __shfl_xor_sync(0xffffffffu, z_hi, 1);
    z_hi += __shfl_xor_sync(0xffffffffu, z_hi, 2);
    const float inv_lo = 1.f / (z_lo + 1e-5f);
    const float inv_hi = 1.f / (z_hi + 1e-5f);

    const int qrow_lo = qt * 128 + goff + wl * 16 + g;
    float* obase = o_ + (size_t)(b * LL) * HID + h * HDIM;
#pragma unroll
    for (int nt = 0; nt < 8; nt++) {
        const int col = nt * 8 + 2 * t;
        *(uint2*)(obase + (size_t)qrow_lo * HID + col) =
            make_uint2(f2tf(oc[nt][0] * inv_lo), f2tf(oc[nt][1] * inv_lo));
        *(uint2*)(obase + (size_t)(qrow_lo + 8) * HID + col) =
            make_uint2(f2tf(oc[nt][2] * inv_hi), f2tf(oc[nt][3] * inv_hi));
    }
}

// ---------------------------------------------------------------------------
extern "C" void kernel_launch(void* const* d_in, const int* in_sizes, int n_in,
                              void* d_out, int out_size) {
    const float* x     = (const float*)d_in[0];   // (2,2048,1024)
    const float* Wq    = (const float*)d_in[1];   // (256,1024)
    const float* Wk    = (const float*)d_in[2];   // (256,1024)
    const float* Wv    = (const float*)d_in[3];   // (1024,1024)
    const float* Wo    = (const float*)d_in[4];   // (1024,1024)
    const float* gamma = (const float*)d_in[5];   // (16,)
    const float* beta  = (const float*)d_in[6];   // (16,)
    float* out = (float*)d_out;

    float *q, *k, *v, *o, *xr, *wqr, *wkr, *wvr, *wor;
    cudaGetSymbolAddress((void**)&q, g_q);
    cudaGetSymbolAddress((void**)&k, g_k);
    cudaGetSymbolAddress((void**)&v, g_v);
    cudaGetSymbolAddress((void**)&o, g_o);
    cudaGetSymbolAddress((void**)&xr, g_xr);
    cudaGetSymbolAddress((void**)&wqr, g_wqr);
    cudaGetSymbolAddress((void**)&wkr, g_wkr);
    cudaGetSymbolAddress((void**)&wvr, g_wvr);
    cudaGetSymbolAddress((void**)&wor, g_wor);

    // Allow 60 KB dynamic smem for the GEMM kernels (attribute, not an alloc)
    const int SMEM_GEMM = 61440;
    cudaFuncSetAttribute(gemm_proj, cudaFuncAttributeMaxDynamicSharedMemorySize, SMEM_GEMM);
    cudaFuncSetAttribute(gemm_tf32_nt, cudaFuncAttributeMaxDynamicSharedMemorySize, SMEM_GEMM);

    // Pre-round GEMM inputs to tf32 (enables raw cp.async into MMA tiles)
    round_inputs<<<592, 256>>>(x, Wq, Wk, Wv, Wo, xr, wqr, wkr, wvr, wor);

    // Fused Q+K(+featmap) and V projections (384 uniform CTAs, BK=16 pipeline)
    gemm_proj<<<dim3(12, 32), 256, SMEM_GEMM>>>(xr, wqr, wkr, wvr, q, k, v, gamma, beta);

    // Tensor-core causal quadratic attention (R10 v4; epilogue rounds o)
    attn_mma<<<dim3(LL / 128, BB * NH), 256>>>(q, k, v, o);

    // Output projection (BK=16 pipeline, pre-rounded inputs)
    gemm_tf32_nt<<<dim3(HID / 128, MTOT / 128), 256, SMEM_GEMM>>>(o, wor, out, HID, HID);
}